// round 1
// baseline (speedup 1.0000x reference)
#include <cuda_runtime.h>
#include <math.h>

#define HD   200
#define POOL 16
#define TLEN 4096
#define NPH  3200   // POOL*HD
#define KW1  400    // 2*HD (U part of W1)

// ---------------- device scratch (static: no allocs allowed) ----------------
__device__ __align__(16) float g_W1uT[2][KW1][NPH];   // [net][k][h*16+p]
__device__ __align__(16) float g_W2T [2][HD][NPH];    // [net][k][h*16+p]
__device__ __align__(16) float g_b2T [2][NPH];
__device__ __align__(16) float g_PU  [2][TLEN][NPH];  // 104 MB
__device__ __align__(16) float g_m1T [2][HD][TLEN];
__device__ __align__(16) float g_m2T [2][HD][TLEN];
__device__ __align__(16) float g_prT [2][NPH];
__device__ float g_g[4 * HD];
__device__ float g_hv[HD];
__device__ float g_cv[HD];
__device__ float g_r[2][HD];
__device__ int   g_s, g_e;

// ---------------- helpers ----------------
__device__ __forceinline__ unsigned long long fma2(unsigned long long a,
                                                   unsigned long long b,
                                                   unsigned long long c) {
    unsigned long long d;
    asm("fma.rn.f32x2 %0, %1, %2, %3;" : "=l"(d) : "l"(a), "l"(b), "l"(c));
    return d;
}
__device__ __forceinline__ unsigned long long pack2(float x) {
    unsigned long long d;
    asm("mov.b64 %0, {%1, %1};" : "=l"(d) : "f"(x));
    return d;
}
__device__ __forceinline__ float2 unpack2(unsigned long long v) {
    float2 r;
    asm("mov.b64 {%0, %1}, %2;" : "=f"(r.x), "=f"(r.y) : "l"(v));
    return r;
}
__device__ __forceinline__ float sigm(float x) { return 1.0f / (1.0f + expf(-x)); }

// ---------------- K0: prep (transposes + state reset), once per launch ----------------
__global__ void prep_kernel(const float* __restrict__ W1a, const float* __restrict__ W1b,
                            const float* __restrict__ W2a, const float* __restrict__ W2b,
                            const float* __restrict__ b2a, const float* __restrict__ b2b,
                            const float* __restrict__ h0,  const float* __restrict__ c0) {
    int idx0 = blockIdx.x * blockDim.x + threadIdx.x;
    int stride = gridDim.x * blockDim.x;
    // W1u transpose: [net][k<400][n=h*16+p] = W1[p][h][k]
    for (int i = idx0; i < 2 * KW1 * NPH; i += stride) {
        int net = i / (KW1 * NPH);
        int rem = i - net * (KW1 * NPH);
        int k = rem / NPH;
        int n = rem - k * NPH;
        int h = n >> 4, p = n & 15;
        const float* W1 = net ? W1b : W1a;
        g_W1uT[net][k][n] = W1[(size_t)(p * HD + h) * 600 + k];
    }
    // W2 transpose: [net][k<200][n=h*16+p] = W2[p][h][k]
    for (int i = idx0; i < 2 * HD * NPH; i += stride) {
        int net = i / (HD * NPH);
        int rem = i - net * (HD * NPH);
        int k = rem / NPH;
        int n = rem - k * NPH;
        int h = n >> 4, p = n & 15;
        const float* W2 = net ? W2b : W2a;
        g_W2T[net][k][n] = W2[(size_t)(p * HD + h) * HD + k];
    }
    // b2 transpose
    for (int i = idx0; i < 2 * NPH; i += stride) {
        int net = i / NPH;
        int n = i - net * NPH;
        int h = n >> 4, p = n & 15;
        const float* b2 = net ? b2b : b2a;
        g_b2T[net][n] = b2[p * HD + h];
    }
    if (idx0 < HD) { g_hv[idx0] = h0[idx0]; g_cv[idx0] = c0[idx0]; }
    if (idx0 == 0) { g_s = 0; g_e = 0; }
}

// ---------------- GEMM: C[m=t][n] = sum_k A[k][m] * B[k][n]  ----------------
// MODE 0: PU precompute  (A = U,   K=400, C = g_PU, plain store)
// MODE 1: W2 pass        (A = m1T, K=200, epilogue: +b2T, max over p -> m2T)
// Block tile 128(m) x 32(n), 128 threads, thread tile 8m x 4n, fma.rn.f32x2 over m-pairs.
template <int MODE>
__global__ void __launch_bounds__(128) gemm_kernel(const float* __restrict__ Uptr) {
    const int net = blockIdx.z;
    const int m0 = blockIdx.x * 128;
    const int n0 = blockIdx.y * 32;
    const int K = (MODE == 0) ? KW1 : HD;
    const float* __restrict__ A = (MODE == 0) ? Uptr : &g_m1T[net][0][0];
    const float* __restrict__ B = (MODE == 0) ? &g_W1uT[net][0][0] : &g_W2T[net][0][0];

    __shared__ float As[16][128];
    __shared__ float Bs[16][32];
    __shared__ float red[8][128];

    const int tid = threadIdx.x;
    const int mg = tid & 15;   // 16 m-groups of 8
    const int ng = tid >> 4;   // 8 n-groups of 4

    unsigned long long acc[4][4];
#pragma unroll
    for (int j = 0; j < 4; j++)
#pragma unroll
        for (int i = 0; i < 4; i++) acc[j][i] = 0ull;

    for (int kc = 0; kc < K; kc += 16) {
        // load A tile: 16x128 floats = 512 float4, 4 per thread
#pragma unroll
        for (int r = 0; r < 4; r++) {
            int fi = tid + r * 128;
            int k = fi >> 5;
            int m = (fi & 31) << 2;
            float4 v = make_float4(0.f, 0.f, 0.f, 0.f);
            if (kc + k < K) v = *(const float4*)&A[(size_t)(kc + k) * TLEN + m0 + m];
            *(float4*)&As[k][m] = v;
        }
        // load B tile: 16x32 floats = 128 float4, 1 per thread
        {
            int k = tid >> 3;
            int n = (tid & 7) << 2;
            float4 v = make_float4(0.f, 0.f, 0.f, 0.f);
            if (kc + k < K) v = *(const float4*)&B[(size_t)(kc + k) * NPH + n0 + n];
            *(float4*)&Bs[k][n] = v;
        }
        __syncthreads();
#pragma unroll
        for (int k = 0; k < 16; k++) {
            ulonglong2 a01 = *(const ulonglong2*)&As[k][mg * 8];
            ulonglong2 a23 = *(const ulonglong2*)&As[k][mg * 8 + 4];
            unsigned long long av0 = a01.x, av1 = a01.y, av2 = a23.x, av3 = a23.y;
            float4 bv = *(const float4*)&Bs[k][ng * 4];
            unsigned long long bb0 = pack2(bv.x), bb1 = pack2(bv.y);
            unsigned long long bb2 = pack2(bv.z), bb3 = pack2(bv.w);
            acc[0][0] = fma2(av0, bb0, acc[0][0]);
            acc[0][1] = fma2(av1, bb0, acc[0][1]);
            acc[0][2] = fma2(av2, bb0, acc[0][2]);
            acc[0][3] = fma2(av3, bb0, acc[0][3]);
            acc[1][0] = fma2(av0, bb1, acc[1][0]);
            acc[1][1] = fma2(av1, bb1, acc[1][1]);
            acc[1][2] = fma2(av2, bb1, acc[1][2]);
            acc[1][3] = fma2(av3, bb1, acc[1][3]);
            acc[2][0] = fma2(av0, bb2, acc[2][0]);
            acc[2][1] = fma2(av1, bb2, acc[2][1]);
            acc[2][2] = fma2(av2, bb2, acc[2][2]);
            acc[2][3] = fma2(av3, bb2, acc[2][3]);
            acc[3][0] = fma2(av0, bb3, acc[3][0]);
            acc[3][1] = fma2(av1, bb3, acc[3][1]);
            acc[3][2] = fma2(av2, bb3, acc[3][2]);
            acc[3][3] = fma2(av3, bb3, acc[3][3]);
        }
        __syncthreads();
    }

    if (MODE == 0) {
        float* C = &g_PU[net][0][0];
#pragma unroll
        for (int i = 0; i < 4; i++) {
            float2 v0 = unpack2(acc[0][i]);
            float2 v1 = unpack2(acc[1][i]);
            float2 v2 = unpack2(acc[2][i]);
            float2 v3 = unpack2(acc[3][i]);
            int m = mg * 8 + i * 2;
            float4 lo = make_float4(v0.x, v1.x, v2.x, v3.x);
            float4 hi = make_float4(v0.y, v1.y, v2.y, v3.y);
            *(float4*)&C[(size_t)(m0 + m) * NPH + n0 + ng * 4] = lo;
            *(float4*)&C[(size_t)(m0 + m + 1) * NPH + n0 + ng * 4] = hi;
        }
    } else {
        float b0 = g_b2T[net][n0 + ng * 4 + 0];
        float b1v = g_b2T[net][n0 + ng * 4 + 1];
        float b2v = g_b2T[net][n0 + ng * 4 + 2];
        float b3v = g_b2T[net][n0 + ng * 4 + 3];
#pragma unroll
        for (int i = 0; i < 4; i++) {
            float2 v0 = unpack2(acc[0][i]);
            float2 v1 = unpack2(acc[1][i]);
            float2 v2 = unpack2(acc[2][i]);
            float2 v3 = unpack2(acc[3][i]);
            float mlo = fmaxf(fmaxf(v0.x + b0, v1.x + b1v), fmaxf(v2.x + b2v, v3.x + b3v));
            float mhi = fmaxf(fmaxf(v0.y + b0, v1.y + b1v), fmaxf(v2.y + b2v, v3.y + b3v));
            red[ng][mg * 8 + i * 2]     = mlo;
            red[ng][mg * 8 + i * 2 + 1] = mhi;
        }
        __syncthreads();
        int hbase = n0 >> 4;  // 2 h values per 32-wide n chunk
        for (int w = tid; w < 256; w += 128) {
            int hh = w >> 7;
            int m = w & 127;
            float v = fmaxf(fmaxf(red[hh * 4 + 0][m], red[hh * 4 + 1][m]),
                            fmaxf(red[hh * 4 + 2][m], red[hh * 4 + 3][m]));
            g_m2T[net][hbase + hh][m0 + m] = v;
        }
    }
}

// ---------------- LSTM gates: g = W_ih@x + b_ih + W_hh@h + b_hh ----------------
__global__ void lstm_gates(const float* __restrict__ U, const float* __restrict__ W_ih,
                           const float* __restrict__ W_hh, const float* __restrict__ b_ih,
                           const float* __restrict__ b_hh) {
    __shared__ float xs[800];
    __shared__ float hs[HD];
    int tid = threadIdx.x;
    int s = g_s, e = g_e;
    for (int j = tid; j < 800; j += 256)
        xs[j] = (j < 400) ? U[(size_t)j * TLEN + s] : U[(size_t)(j - 400) * TLEN + e];
    for (int j = tid; j < HD; j += 256) hs[j] = g_hv[j];
    __syncthreads();
    int row = blockIdx.x * 8 + (tid >> 5);
    int lane = tid & 31;
    const float* wr = &W_ih[(size_t)row * 800];
    float acc = 0.f;
    for (int k = lane; k < 800; k += 32) acc += wr[k] * xs[k];
    const float* wh = &W_hh[(size_t)row * HD];
    for (int k = lane; k < HD; k += 32) acc += wh[k] * hs[k];
#pragma unroll
    for (int o = 16; o; o >>= 1) acc += __shfl_xor_sync(0xffffffffu, acc, o);
    if (lane == 0) g_g[row] = acc + b_ih[row] + b_hh[row];
}

__global__ void lstm_update() {
    int i = threadIdx.x;
    if (i < HD) {
        float gi = g_g[i], gf = g_g[HD + i], gg = g_g[2 * HD + i], go = g_g[3 * HD + i];
        float c = sigm(gf) * g_cv[i] + sigm(gi) * tanhf(gg);
        float h = sigm(go) * tanhf(c);
        g_cv[i] = c;
        g_hv[i] = h;
    }
}

// ---------------- r = tanh(WD @ [h, u_s, u_e]) for both nets ----------------
__global__ void r_kernel(const float* __restrict__ U, const float* __restrict__ WDa,
                         const float* __restrict__ WDb) {
    __shared__ float vs[1000];
    int tid = threadIdx.x;
    int s = g_s, e = g_e;
    for (int j = tid; j < 1000; j += 256) {
        float v;
        if (j < HD) v = g_hv[j];
        else if (j < HD + 400) v = U[(size_t)(j - HD) * TLEN + s];
        else v = U[(size_t)(j - HD - 400) * TLEN + e];
        vs[j] = v;
    }
    __syncthreads();
    int row = blockIdx.x * 8 + (tid >> 5);  // 0..399
    int lane = tid & 31;
    int net = row / HD;
    int rr = row - net * HD;
    const float* WD = net ? WDb : WDa;
    const float* wr = &WD[(size_t)rr * 1000];
    float acc = 0.f;
    for (int k = lane; k < 1000; k += 32) acc += wr[k] * vs[k];
#pragma unroll
    for (int o = 16; o; o >>= 1) acc += __shfl_xor_sync(0xffffffffu, acc, o);
    if (lane == 0) g_r[net][rr] = tanhf(acc);
}

// ---------------- prT[net][h*16+p] = W1r[p][h]@r + b1[p][h] ----------------
__global__ void pr_kernel(const float* __restrict__ W1a, const float* __restrict__ W1b,
                          const float* __restrict__ b1a, const float* __restrict__ b1b) {
    int o = blockIdx.x * 8 + (threadIdx.x >> 5);  // 0..6399
    int lane = threadIdx.x & 31;
    int net = o / NPH;
    int n = o - net * NPH;
    int h = n >> 4, p = n & 15;
    const float* W1 = net ? W1b : W1a;
    const float* b1 = net ? b1b : b1a;
    const float* w = &W1[(size_t)(p * HD + h) * 600 + 400];
    const float* r = g_r[net];
    float acc = 0.f;
    for (int k = lane; k < HD; k += 32) acc += w[k] * r[k];
#pragma unroll
    for (int o2 = 16; o2; o2 >>= 1) acc += __shfl_xor_sync(0xffffffffu, acc, o2);
    if (lane == 0) g_prT[net][n] = acc + b1[p * HD + h];
}

// ---------------- m1T[net][h][t] = max_p (PU[net][t][h*16+p] + prT[net][h*16+p]) ----------------
__global__ void m1_kernel() {
    int idx = blockIdx.x * blockDim.x + threadIdx.x;  // 2*200*4096 = 1638400
    int t = idx & (TLEN - 1);
    int hn = idx >> 12;
    int h = hn % HD;
    int net = hn / HD;
    if (net >= 2) return;
    const float4* pu = (const float4*)&g_PU[net][t][h << 4];
    const float4* pr = (const float4*)&g_prT[net][h << 4];
    float m = -3.4e38f;
#pragma unroll
    for (int q = 0; q < 4; q++) {
        float4 a = pu[q], b = pr[q];
        m = fmaxf(m, fmaxf(fmaxf(a.x + b.x, a.y + b.y), fmaxf(a.z + b.z, a.w + b.w)));
    }
    g_m1T[net][h][t] = m;
}

// ---------------- scores: alpha[t] = max_p ( [m1,m2] . W3[p] + b3[p] ) ----------------
__global__ void score_kernel(const float* __restrict__ W3a, const float* __restrict__ W3b,
                             const float* __restrict__ b3a, const float* __restrict__ b3b,
                             float* __restrict__ out, int it, int maxI) {
    __shared__ float ms[400][9];
    __shared__ float w3s[16][401];
    int net = blockIdx.y;
    int t0 = blockIdx.x * 8;
    int tid = threadIdx.x;
    const float* W3 = net ? W3b : W3a;
    for (int idx = tid; idx < 3200; idx += 128) {
        int h = idx >> 3, tt = idx & 7;
        ms[h][tt] = (h < HD) ? g_m1T[net][h][t0 + tt] : g_m2T[net][h - HD][t0 + tt];
    }
    for (int idx = tid; idx < 6400; idx += 128) {
        int p = idx / 400, d = idx - p * 400;
        w3s[p][d] = W3[p * 400 + d];
    }
    __syncthreads();
    int tt = tid >> 4, p = tid & 15;
    const float* b3 = net ? b3b : b3a;
    float acc = b3[p];
#pragma unroll 4
    for (int h = 0; h < 400; h++) acc = fmaf(ms[h][tt], w3s[p][h], acc);
#pragma unroll
    for (int o = 8; o; o >>= 1) acc = fmaxf(acc, __shfl_xor_sync(0xffffffffu, acc, o));
    if (p == 0) out[((size_t)net * maxI + it) * TLEN + t0 + tt] = acc;
}

// ---------------- argmax over t (first-index tie-break), update s/e ----------------
__global__ void argmax_kernel(float* __restrict__ out, int it, int maxI, int last) {
    int net = blockIdx.x;
    const float* a = &out[((size_t)net * maxI + it) * TLEN];
    int tid = threadIdx.x;
    float bv = -3.4e38f;
    int bi = 0x7fffffff;
    for (int t = tid; t < TLEN; t += 1024) {
        float v = a[t];
        if (v > bv || (v == bv && t < bi)) { bv = v; bi = t; }
    }
    __shared__ float sv[1024];
    __shared__ int si[1024];
    sv[tid] = bv;
    si[tid] = bi;
    __syncthreads();
    for (int s2 = 512; s2; s2 >>= 1) {
        if (tid < s2) {
            float v2 = sv[tid + s2];
            int i2 = si[tid + s2];
            if (v2 > sv[tid] || (v2 == sv[tid] && i2 < si[tid])) { sv[tid] = v2; si[tid] = i2; }
        }
        __syncthreads();
    }
    if (tid == 0) {
        if (net == 0) g_s = si[0];
        else g_e = si[0];
        if (last) out[(size_t)2 * maxI * TLEN + net] = (float)si[0];
    }
}

// ---------------- launch ----------------
extern "C" void kernel_launch(void* const* d_in, const int* in_sizes, int n_in,
                              void* d_out, int out_size) {
    const float* U    = (const float*)d_in[0];
    // d_in[1] = max_iter (device scalar; iteration count derived from out_size instead)
    const float* h0   = (const float*)d_in[2];
    const float* c0   = (const float*)d_in[3];
    const float* W_ih = (const float*)d_in[4];
    const float* W_hh = (const float*)d_in[5];
    const float* b_ih = (const float*)d_in[6];
    const float* b_hh = (const float*)d_in[7];
    const float* WD_a = (const float*)d_in[8];
    const float* W1_a = (const float*)d_in[9];
    const float* b1_a = (const float*)d_in[10];
    const float* W2_a = (const float*)d_in[11];
    const float* b2_a = (const float*)d_in[12];
    const float* W3_a = (const float*)d_in[13];
    const float* b3_a = (const float*)d_in[14];
    const float* WD_b = (const float*)d_in[15];
    const float* W1_b = (const float*)d_in[16];
    const float* b1_b = (const float*)d_in[17];
    const float* W2_b = (const float*)d_in[18];
    const float* b2_b = (const float*)d_in[19];
    const float* W3_b = (const float*)d_in[20];
    const float* b3_b = (const float*)d_in[21];
    float* out = (float*)d_out;

    int maxI = out_size / (2 * TLEN);
    if (maxI < 1) maxI = 1;
    int write_se = (out_size >= 2 * maxI * TLEN + 2) ? 1 : 0;

    prep_kernel<<<1024, 256>>>(W1_a, W1_b, W2_a, W2_b, b2_a, b2_b, h0, c0);
    gemm_kernel<0><<<dim3(TLEN / 128, NPH / 32, 2), 128>>>(U);

    for (int it = 0; it < maxI; it++) {
        lstm_gates<<<100, 256>>>(U, W_ih, W_hh, b_ih, b_hh);
        lstm_update<<<1, 256>>>();
        r_kernel<<<50, 256>>>(U, WD_a, WD_b);
        pr_kernel<<<800, 256>>>(W1_a, W1_b, b1_a, b1_b);
        m1_kernel<<<6400, 256>>>();
        gemm_kernel<1><<<dim3(TLEN / 128, NPH / 32, 2), 128>>>(U);
        score_kernel<<<dim3(TLEN / 8, 2), 128>>>(W3_a, W3_b, b3_a, b3_b, out, it, maxI);
        argmax_kernel<<<2, 1024>>>(out, it, maxI, (it == maxI - 1) ? write_se : 0);
    }
}

// round 3
// speedup vs baseline: 2.5412x; 2.5412x over previous
#include <cuda_runtime.h>
#include <cuda_bf16.h>
#include <math.h>
#include <stdint.h>

#define HD    200
#define POOL  16
#define TLEN  4096
#define NPH   3200   // POOL*HD
#define K1PAD 416    // pad of 2*HD=400 to mult of 32
#define K2PAD 224    // pad of HD=200 to mult of 32

// ------------------------------------------------------------------
// Static device scratch (no allocations allowed)
// ------------------------------------------------------------------
__device__ __align__(16) __nv_bfloat16 g_UThi[TLEN][K1PAD];      // A1  [t][k]
__device__ __align__(16) __nv_bfloat16 g_UTlo[TLEN][K1PAD];
__device__ __align__(16) __nv_bfloat16 g_B1hi[2][K1PAD][NPH];    // B1  [k][n]
__device__ __align__(16) __nv_bfloat16 g_B1lo[2][K1PAD][NPH];
__device__ __align__(16) __nv_bfloat16 g_B2hi[2][K2PAD][NPH];    // B2  [k][n]
__device__ __align__(16) __nv_bfloat16 g_B2lo[2][K2PAD][NPH];
__device__ __align__(16) __nv_bfloat16 g_m1hi[2][TLEN][K2PAD];   // A2  [t][k]
__device__ __align__(16) __nv_bfloat16 g_m1lo[2][TLEN][K2PAD];
__device__ __align__(16) float g_PU[2][TLEN][NPH];               // fp32, 104 MB
__device__ __align__(16) float g_m2[2][TLEN][HD];
__device__ __align__(16) float g_b2T[2][NPH];
__device__ __align__(16) float g_prT[2][NPH];
__device__ float g_g[4 * HD];
__device__ float g_hv[HD];
__device__ float g_cv[HD];
__device__ float g_r[2][HD];
__device__ int   g_s, g_e;

// ------------------------------------------------------------------
// helpers
// ------------------------------------------------------------------
__device__ __forceinline__ uint32_t smem_u32(const void* p) {
    uint32_t a;
    asm("{ .reg .u64 t; cvta.to.shared.u64 t, %1; cvt.u32.u64 %0, t; }" : "=r"(a) : "l"(p));
    return a;
}
__device__ __forceinline__ void cp16(uint32_t dst, const void* src) {
    asm volatile("cp.async.cg.shared.global [%0], [%1], 16;" :: "r"(dst), "l"(src));
}
#define CP_COMMIT() asm volatile("cp.async.commit_group;" ::: "memory")
#define CP_WAIT0()  asm volatile("cp.async.wait_group 0;" ::: "memory")

__device__ __forceinline__ void ldsm4(uint32_t* r, uint32_t addr) {
    asm volatile("ldmatrix.sync.aligned.m8n8.x4.shared.b16 {%0,%1,%2,%3}, [%4];"
                 : "=r"(r[0]), "=r"(r[1]), "=r"(r[2]), "=r"(r[3]) : "r"(addr));
}
__device__ __forceinline__ void ldsm4t(uint32_t* r, uint32_t addr) {
    asm volatile("ldmatrix.sync.aligned.m8n8.x4.trans.shared.b16 {%0,%1,%2,%3}, [%4];"
                 : "=r"(r[0]), "=r"(r[1]), "=r"(r[2]), "=r"(r[3]) : "r"(addr));
}
__device__ __forceinline__ void mma_bf16(float* c, const uint32_t* a, const uint32_t* b) {
    asm volatile(
        "mma.sync.aligned.m16n8k16.row.col.f32.bf16.bf16.f32 "
        "{%0,%1,%2,%3}, {%4,%5,%6,%7}, {%8,%9}, {%0,%1,%2,%3};"
        : "+f"(c[0]), "+f"(c[1]), "+f"(c[2]), "+f"(c[3])
        : "r"(a[0]), "r"(a[1]), "r"(a[2]), "r"(a[3]), "r"(b[0]), "r"(b[1]));
}
__device__ __forceinline__ float sigm(float x) { return 1.0f / (1.0f + expf(-x)); }
__device__ __forceinline__ void split_bf16(float v, __nv_bfloat16& hi, __nv_bfloat16& lo) {
    hi = __float2bfloat16(v);
    lo = __float2bfloat16(v - __bfloat162float(hi));
}

// ------------------------------------------------------------------
// prep: build bf16 hi/lo operands (A row-major [t][k], B [k][n]) + state
// ------------------------------------------------------------------
__global__ void prep_kernel(const float* __restrict__ W1a, const float* __restrict__ W1b,
                            const float* __restrict__ W2a, const float* __restrict__ W2b,
                            const float* __restrict__ b2a, const float* __restrict__ b2b,
                            const float* __restrict__ h0,  const float* __restrict__ c0,
                            const float* __restrict__ U) {
    int idx0 = blockIdx.x * blockDim.x + threadIdx.x;
    int stride = gridDim.x * blockDim.x;
    // U^T -> [t][k], k padded to 416
    for (int i = idx0; i < TLEN * K1PAD; i += stride) {
        int t = i / K1PAD, k = i - t * K1PAD;
        float v = (k < 2 * HD) ? U[(size_t)k * TLEN + t] : 0.f;
        __nv_bfloat16 hi, lo; split_bf16(v, hi, lo);
        g_UThi[t][k] = hi; g_UTlo[t][k] = lo;
    }
    // W1 (U part) -> B1[net][k][n=h*16+p]
    for (int i = idx0; i < 2 * K1PAD * NPH; i += stride) {
        int net = i / (K1PAD * NPH);
        int rem = i - net * (K1PAD * NPH);
        int k = rem / NPH, n = rem - k * NPH;
        int h = n >> 4, p = n & 15;
        const float* W1 = net ? W1b : W1a;
        float v = (k < 2 * HD) ? W1[(size_t)(p * HD + h) * 600 + k] : 0.f;
        __nv_bfloat16 hi, lo; split_bf16(v, hi, lo);
        g_B1hi[net][k][n] = hi; g_B1lo[net][k][n] = lo;
    }
    // W2 -> B2[net][k][n]
    for (int i = idx0; i < 2 * K2PAD * NPH; i += stride) {
        int net = i / (K2PAD * NPH);
        int rem = i - net * (K2PAD * NPH);
        int k = rem / NPH, n = rem - k * NPH;
        int h = n >> 4, p = n & 15;
        const float* W2 = net ? W2b : W2a;
        float v = (k < HD) ? W2[(size_t)(p * HD + h) * HD + k] : 0.f;
        __nv_bfloat16 hi, lo; split_bf16(v, hi, lo);
        g_B2hi[net][k][n] = hi; g_B2lo[net][k][n] = lo;
    }
    // b2 transposed to n=h*16+p
    for (int i = idx0; i < 2 * NPH; i += stride) {
        int net = i / NPH, n = i - net * NPH;
        int h = n >> 4, p = n & 15;
        const float* b2 = net ? b2b : b2a;
        g_b2T[net][n] = b2[p * HD + h];
    }
    // zero m1 K pad (k in [200,224))
    for (int i = idx0; i < 2 * TLEN * (K2PAD - HD); i += stride) {
        int net = i / (TLEN * (K2PAD - HD));
        int rem = i - net * (TLEN * (K2PAD - HD));
        int t = rem / (K2PAD - HD);
        int k = HD + (rem - t * (K2PAD - HD));
        __nv_bfloat16 z = __float2bfloat16(0.f);
        g_m1hi[net][t][k] = z; g_m1lo[net][t][k] = z;
    }
    if (idx0 < HD) { g_hv[idx0] = h0[idx0]; g_cv[idx0] = c0[idx0]; }
    if (idx0 == 0) { g_s = 0; g_e = 0; }
}

// ------------------------------------------------------------------
// mma.sync GEMM: C[t][n] = sum_k A[t][k]*B[k][n], 2-way bf16 split
// MODE 0: A=UT (K=416), B=B1 -> fp32 store to g_PU
// MODE 1: A=m1 (K=224), B=B2 -> epilogue +b2T, max over p -> g_m2[t][h]
// Block tile 128(m) x 64(n), 256 threads (8 warps, 4m x 2n, 32x32/warp),
// K-chunk 32, 2-stage cp.async pipeline.
// ------------------------------------------------------------------
// smem layout (bytes):
//  As_hi: 2 stages x 128 rows x 40 halves (80B rows)  = 20480
//  As_lo: +20480
//  Bs_hi: 2 stages x 32 rows x 72 halves (144B rows)  =  9216  @40960
//  Bs_lo: @50176
#define A_ROW_B   80
#define A_STG_B   10240
#define B_ROW_B   144
#define B_STG_B   4608
#define OFF_ALO   20480
#define OFF_BHI   40960
#define OFF_BLO   50176
#define GEMM_SMEM 59392

template <int MODE>
__global__ void __launch_bounds__(256) gemm_mma() {
    extern __shared__ char smem[];
    const int tid    = threadIdx.x;
    const int lane   = tid & 31;
    const int wid    = tid >> 5;
    const int warp_m = wid & 3;     // 4 m-quadrants of 32 rows
    const int warp_n = wid >> 2;    // 2 n-halves of 32 cols
    const int net    = blockIdx.z;
    const int m0     = blockIdx.x * 128;
    const int n0     = blockIdx.y * 64;
    const int KPAD   = (MODE == 0) ? K1PAD : K2PAD;
    const int NC     = KPAD / 32;

    const __nv_bfloat16* __restrict__ Ahi = (MODE == 0) ? &g_UThi[0][0] : &g_m1hi[net][0][0];
    const __nv_bfloat16* __restrict__ Alo = (MODE == 0) ? &g_UTlo[0][0] : &g_m1lo[net][0][0];
    const __nv_bfloat16* __restrict__ Bhi = (MODE == 0) ? &g_B1hi[net][0][0] : &g_B2hi[net][0][0];
    const __nv_bfloat16* __restrict__ Blo = (MODE == 0) ? &g_B1lo[net][0][0] : &g_B2lo[net][0][0];

    const uint32_t sb = smem_u32(smem);

    // per-thread load mapping
    const int arow = tid >> 1;            // A: 2 chunks of 16B per row pair-thread
    const int aq   = (tid & 1) * 2;       // quarters {0,1} or {2,3}
    const int brow = tid >> 3;            // B: 32 rows x 8 chunks
    const int bq   = tid & 7;

    auto load_stage = [&](int stage, int kc) {
        const uint32_t as = sb + stage * A_STG_B + arow * A_ROW_B + aq * 16;
        const __nv_bfloat16* ah = Ahi + (size_t)(m0 + arow) * KPAD + kc + aq * 8;
        const __nv_bfloat16* al = Alo + (size_t)(m0 + arow) * KPAD + kc + aq * 8;
        cp16(as,               ah);
        cp16(as + 16,          ah + 8);
        cp16(as + OFF_ALO,     al);
        cp16(as + OFF_ALO + 16, al + 8);
        const uint32_t bs = sb + OFF_BHI + stage * B_STG_B + brow * B_ROW_B + bq * 16;
        const __nv_bfloat16* bh = Bhi + (size_t)(kc + brow) * NPH + n0 + bq * 8;
        const __nv_bfloat16* bl = Blo + (size_t)(kc + brow) * NPH + n0 + bq * 8;
        cp16(bs,                        bh);
        cp16(bs + (OFF_BLO - OFF_BHI),  bl);
    };

    float acc[2][4][4];
#pragma unroll
    for (int i = 0; i < 2; i++)
#pragma unroll
        for (int j = 0; j < 4; j++)
#pragma unroll
            for (int q = 0; q < 4; q++) acc[i][j][q] = 0.f;

    // ldmatrix per-lane address bases (byte offsets within a stage)
    const int l15 = lane & 15;
    const int l16 = (lane >> 4) * 8;      // +8 cols for upper half-warp
    // A: row = warp_m*32 + i*16 + l15, col halves = s*16 + l16
    const uint32_t aBase = sb + (warp_m * 32 + l15) * A_ROW_B + l16 * 2;
    // B: row(k) = s*16 + l15, col halves = warp_n*32 + pair*16 + l16
    const uint32_t bBase = sb + OFF_BHI + l15 * B_ROW_B + (warp_n * 32 + l16) * 2;

    load_stage(0, 0);
    CP_COMMIT();

    for (int c = 0; c < NC; c++) {
        CP_WAIT0();
        __syncthreads();
        if (c + 1 < NC) { load_stage((c + 1) & 1, (c + 1) * 32); CP_COMMIT(); }
        const int stg = c & 1;
        const uint32_t aS = aBase + stg * A_STG_B;
        const uint32_t bS = bBase + stg * B_STG_B;
#pragma unroll
        for (int s = 0; s < 2; s++) {
            uint32_t ah[2][4], al[2][4], bh[4][2], bl[4][2];
#pragma unroll
            for (int i = 0; i < 2; i++) {
                uint32_t ao = aS + i * 16 * A_ROW_B + s * 32;
                ldsm4(ah[i], ao);
                ldsm4(al[i], ao + OFF_ALO);
            }
#pragma unroll
            for (int pr = 0; pr < 2; pr++) {
                uint32_t bo = bS + s * 16 * B_ROW_B + pr * 32;
                uint32_t r[4];
                ldsm4t(r, bo);
                bh[pr * 2][0] = r[0]; bh[pr * 2][1] = r[1];
                bh[pr * 2 + 1][0] = r[2]; bh[pr * 2 + 1][1] = r[3];
                ldsm4t(r, bo + (OFF_BLO - OFF_BHI));
                bl[pr * 2][0] = r[0]; bl[pr * 2][1] = r[1];
                bl[pr * 2 + 1][0] = r[2]; bl[pr * 2 + 1][1] = r[3];
            }
#pragma unroll
            for (int i = 0; i < 2; i++)
#pragma unroll
                for (int j = 0; j < 4; j++) {
                    mma_bf16(acc[i][j], ah[i], bh[j]);
                    mma_bf16(acc[i][j], ah[i], bl[j]);
                    mma_bf16(acc[i][j], al[i], bh[j]);
                }
        }
        __syncthreads();
    }

    // epilogue
    const int g4 = lane >> 2;           // 0..7
    const int t2 = (lane & 3) * 2;      // even col within 8-tile
    if (MODE == 0) {
        float* C = &g_PU[net][0][0];
#pragma unroll
        for (int i = 0; i < 2; i++) {
            int r0 = m0 + warp_m * 32 + i * 16 + g4;
#pragma unroll
            for (int j = 0; j < 4; j++) {
                int col = n0 + warp_n * 32 + j * 8 + t2;
                *(float2*)&C[(size_t)r0 * NPH + col] =
                    make_float2(acc[i][j][0], acc[i][j][1]);
                *(float2*)&C[(size_t)(r0 + 8) * NPH + col] =
                    make_float2(acc[i][j][2], acc[i][j][3]);
            }
        }
    } else {
        // +b2, max over p (16 n-cols = 2 ntile-pairs per h)
        float b2v[4][2];
#pragma unroll
        for (int j = 0; j < 4; j++) {
            int col = n0 + warp_n * 32 + j * 8 + t2;
            b2v[j][0] = __ldg(&g_b2T[net][col]);
            b2v[j][1] = __ldg(&g_b2T[net][col + 1]);
        }
        const int h0 = (n0 + warp_n * 32) >> 4;
#pragma unroll
        for (int i = 0; i < 2; i++) {
#pragma unroll
            for (int hh = 0; hh < 2; hh++) {
                float mx0 = -3.4e38f, mx1 = -3.4e38f;
#pragma unroll
                for (int j = 0; j < 4; j++) {
                    float v0 = acc[i][j][hh * 2]     + b2v[j][0];
                    float v1 = acc[i][j][hh * 2 + 1] + b2v[j][1];
                    float m = fmaxf(v0, v1);
                    if (j < 2) mx0 = fmaxf(mx0, m); else mx1 = fmaxf(mx1, m);
                }
                mx0 = fmaxf(mx0, __shfl_xor_sync(0xffffffffu, mx0, 1));
                mx0 = fmaxf(mx0, __shfl_xor_sync(0xffffffffu, mx0, 2));
                mx1 = fmaxf(mx1, __shfl_xor_sync(0xffffffffu, mx1, 1));
                mx1 = fmaxf(mx1, __shfl_xor_sync(0xffffffffu, mx1, 2));
                if ((lane & 3) == 0) {
                    int row = m0 + warp_m * 32 + i * 16 + hh * 8 + g4;
                    g_m2[net][row][h0]     = mx0;
                    g_m2[net][row][h0 + 1] = mx1;
                }
            }
        }
    }
}

// ------------------------------------------------------------------
// LSTM gates + update
// ------------------------------------------------------------------
__global__ void lstm_gates(const float* __restrict__ U, const float* __restrict__ W_ih,
                           const float* __restrict__ W_hh, const float* __restrict__ b_ih,
                           const float* __restrict__ b_hh) {
    __shared__ float xs[800];
    __shared__ float hs[HD];
    int tid = threadIdx.x;
    int s = g_s, e = g_e;
    for (int j = tid; j < 800; j += 256)
        xs[j] = (j < 400) ? U[(size_t)j * TLEN + s] : U[(size_t)(j - 400) * TLEN + e];
    for (int j = tid; j < HD; j += 256) hs[j] = g_hv[j];
    __syncthreads();
    int row = blockIdx.x * 8 + (tid >> 5);
    int lane = tid & 31;
    const float* wr = &W_ih[(size_t)row * 800];
    float acc = 0.f;
    for (int k = lane; k < 800; k += 32) acc += wr[k] * xs[k];
    const float* wh = &W_hh[(size_t)row * HD];
    for (int k = lane; k < HD; k += 32) acc += wh[k] * hs[k];
#pragma unroll
    for (int o = 16; o; o >>= 1) acc += __shfl_xor_sync(0xffffffffu, acc, o);
    if (lane == 0) g_g[row] = acc + b_ih[row] + b_hh[row];
}

__global__ void lstm_update() {
    int i = threadIdx.x;
    if (i < HD) {
        float gi = g_g[i], gf = g_g[HD + i], gg = g_g[2 * HD + i], go = g_g[3 * HD + i];
        float c = sigm(gf) * g_cv[i] + sigm(gi) * tanhf(gg);
        float h = sigm(go) * tanhf(c);
        g_cv[i] = c;
        g_hv[i] = h;
    }
}

// ------------------------------------------------------------------
// r = tanh(WD @ [h, u_s, u_e]) for both nets
// ------------------------------------------------------------------
__global__ void r_kernel(const float* __restrict__ U, const float* __restrict__ WDa,
                         const float* __restrict__ WDb) {
    __shared__ float vs[1000];
    int tid = threadIdx.x;
    int s = g_s, e = g_e;
    for (int j = tid; j < 1000; j += 256) {
        float v;
        if (j < HD) v = g_hv[j];
        else if (j < HD + 400) v = U[(size_t)(j - HD) * TLEN + s];
        else v = U[(size_t)(j - HD - 400) * TLEN + e];
        vs[j] = v;
    }
    __syncthreads();
    int row = blockIdx.x * 8 + (tid >> 5);
    int lane = tid & 31;
    int net = row / HD;
    int rr = row - net * HD;
    const float* WD = net ? WDb : WDa;
    const float* wr = &WD[(size_t)rr * 1000];
    float acc = 0.f;
    for (int k = lane; k < 1000; k += 32) acc += wr[k] * vs[k];
#pragma unroll
    for (int o = 16; o; o >>= 1) acc += __shfl_xor_sync(0xffffffffu, acc, o);
    if (lane == 0) g_r[net][rr] = tanhf(acc);
}

// ------------------------------------------------------------------
// prT[net][h*16+p] = W1r[p][h]@r + b1[p][h]
// ------------------------------------------------------------------
__global__ void pr_kernel(const float* __restrict__ W1a, const float* __restrict__ W1b,
                          const float* __restrict__ b1a, const float* __restrict__ b1b) {
    int o = blockIdx.x * 8 + (threadIdx.x >> 5);
    int lane = threadIdx.x & 31;
    int net = o / NPH;
    int n = o - net * NPH;
    int h = n >> 4, p = n & 15;
    const float* W1 = net ? W1b : W1a;
    const float* b1 = net ? b1b : b1a;
    const float* w = &W1[(size_t)(p * HD + h) * 600 + 400];
    const float* r = g_r[net];
    float acc = 0.f;
    for (int k = lane; k < HD; k += 32) acc += w[k] * r[k];
#pragma unroll
    for (int o2 = 16; o2; o2 >>= 1) acc += __shfl_xor_sync(0xffffffffu, acc, o2);
    if (lane == 0) g_prT[net][n] = acc + b1[p * HD + h];
}

// ------------------------------------------------------------------
// m1[t][h] = max_p(PU[t][h*16+p] + prT[h*16+p]) -> hi/lo bf16
// ------------------------------------------------------------------
__global__ void m1_kernel() {
    int t = blockIdx.x, net = blockIdx.y;
    int h = threadIdx.x;
    if (h >= HD) return;
    const float4* pu = (const float4*)&g_PU[net][t][h << 4];
    const float4* pr = (const float4*)&g_prT[net][h << 4];
    float m = -3.4e38f;
#pragma unroll
    for (int q = 0; q < 4; q++) {
        float4 a = pu[q], b = pr[q];
        m = fmaxf(m, fmaxf(fmaxf(a.x + b.x, a.y + b.y), fmaxf(a.z + b.z, a.w + b.w)));
    }
    __nv_bfloat16 hi, lo; split_bf16(m, hi, lo);
    g_m1hi[net][t][h] = hi;
    g_m1lo[net][t][h] = lo;
}

// ------------------------------------------------------------------
// scores: alpha[t] = max_p([m1,m2].W3[p] + b3[p])
// ------------------------------------------------------------------
__global__ void score_kernel(const float* __restrict__ W3a, const float* __restrict__ W3b,
                             const float* __restrict__ b3a, const float* __restrict__ b3b,
                             float* __restrict__ out, int it, int maxI) {
    __shared__ float ms[8][408];
    __shared__ float w3s[16][401];
    int net = blockIdx.y;
    int t0 = blockIdx.x * 8;
    int tid = threadIdx.x;
    const float* W3 = net ? W3b : W3a;
    for (int idx = tid; idx < 6400; idx += 128) {
        int p = idx / 400, d = idx - p * 400;
        w3s[p][d] = W3[p * 400 + d];
    }
    for (int idx = tid; idx < 1600; idx += 128) {
        int tt = idx / 200, h = idx - tt * 200;
        int t = t0 + tt;
        ms[tt][h] = __bfloat162float(g_m1hi[net][t][h]) + __bfloat162float(g_m1lo[net][t][h]);
        ms[tt][200 + h] = g_m2[net][t][h];
    }
    __syncthreads();
    int tt = tid >> 4, p = tid & 15;
    float acc = (net ? b3b : b3a)[p];
#pragma unroll 4
    for (int d = 0; d < 400; d++) acc = fmaf(ms[tt][d], w3s[p][d], acc);
#pragma unroll
    for (int o = 8; o; o >>= 1) acc = fmaxf(acc, __shfl_xor_sync(0xffffffffu, acc, o));
    if (p == 0) out[((size_t)net * maxI + it) * TLEN + t0 + tt] = acc;
}

// ------------------------------------------------------------------
// argmax over t (first-index tie-break), update s/e
// ------------------------------------------------------------------
__global__ void argmax_kernel(float* __restrict__ out, int it, int maxI, int last) {
    int net = blockIdx.x;
    const float* a = &out[((size_t)net * maxI + it) * TLEN];
    int tid = threadIdx.x;
    float bv = -3.4e38f;
    int bi = 0x7fffffff;
    for (int t = tid; t < TLEN; t += 1024) {
        float v = a[t];
        if (v > bv || (v == bv && t < bi)) { bv = v; bi = t; }
    }
    __shared__ float sv[1024];
    __shared__ int si[1024];
    sv[tid] = bv;
    si[tid] = bi;
    __syncthreads();
    for (int s2 = 512; s2; s2 >>= 1) {
        if (tid < s2) {
            float v2 = sv[tid + s2];
            int i2 = si[tid + s2];
            if (v2 > sv[tid] || (v2 == sv[tid] && i2 < si[tid])) { sv[tid] = v2; si[tid] = i2; }
        }
        __syncthreads();
    }
    if (tid == 0) {
        if (net == 0) g_s = si[0];
        else g_e = si[0];
        if (last) out[(size_t)2 * maxI * TLEN + net] = (float)si[0];
    }
}

// ------------------------------------------------------------------
// launch
// ------------------------------------------------------------------
extern "C" void kernel_launch(void* const* d_in, const int* in_sizes, int n_in,
                              void* d_out, int out_size) {
    const float* U    = (const float*)d_in[0];
    const float* h0   = (const float*)d_in[2];
    const float* c0   = (const float*)d_in[3];
    const float* W_ih = (const float*)d_in[4];
    const float* W_hh = (const float*)d_in[5];
    const float* b_ih = (const float*)d_in[6];
    const float* b_hh = (const float*)d_in[7];
    const float* WD_a = (const float*)d_in[8];
    const float* W1_a = (const float*)d_in[9];
    const float* b1_a = (const float*)d_in[10];
    const float* W2_a = (const float*)d_in[11];
    const float* b2_a = (const float*)d_in[12];
    const float* W3_a = (const float*)d_in[13];
    const float* b3_a = (const float*)d_in[14];
    const float* WD_b = (const float*)d_in[15];
    const float* W1_b = (const float*)d_in[16];
    const float* b1_b = (const float*)d_in[17];
    const float* W2_b = (const float*)d_in[18];
    const float* b2_b = (const float*)d_in[19];
    const float* W3_b = (const float*)d_in[20];
    const float* b3_b = (const float*)d_in[21];
    float* out = (float*)d_out;

    int maxI = out_size / (2 * TLEN);
    if (maxI < 1) maxI = 1;
    int write_se = (out_size >= 2 * maxI * TLEN + 2) ? 1 : 0;

    cudaFuncSetAttribute(gemm_mma<0>, cudaFuncAttributeMaxDynamicSharedMemorySize, GEMM_SMEM);
    cudaFuncSetAttribute(gemm_mma<1>, cudaFuncAttributeMaxDynamicSharedMemorySize, GEMM_SMEM);

    prep_kernel<<<2048, 256>>>(W1_a, W1_b, W2_a, W2_b, b2_a, b2_b, h0, c0, U);
    gemm_mma<0><<<dim3(TLEN / 128, NPH / 64, 2), 256, GEMM_SMEM>>>();

    for (int it = 0; it < maxI; it++) {
        lstm_gates<<<100, 256>>>(U, W_ih, W_hh, b_ih, b_hh);
        lstm_update<<<1, 256>>>();
        r_kernel<<<50, 256>>>(U, WD_a, WD_b);
        pr_kernel<<<800, 256>>>(W1_a, W1_b, b1_a, b1_b);
        m1_kernel<<<dim3(TLEN, 2), 256>>>();
        gemm_mma<1><<<dim3(TLEN / 128, NPH / 64, 2), 256, GEMM_SMEM>>>();
        score_kernel<<<dim3(TLEN / 8, 2), 128>>>(W3_a, W3_b, b3_a, b3_b, out, it, maxI);
        argmax_kernel<<<2, 1024>>>(out, it, maxI, (it == maxI - 1) ? write_se : 0);
    }
}

// round 4
// speedup vs baseline: 3.0192x; 1.1881x over previous
#include <cuda_runtime.h>
#include <cuda_fp16.h>
#include <math.h>
#include <stdint.h>

#define HD    200
#define POOL  16
#define TLEN  4096
#define NPH   3200   // POOL*HD
#define K1PAD 416    // pad of 2*HD=400 to mult of 32
#define K2PAD 224    // pad of HD=200 to mult of 32

// ------------------------------------------------------------------
// Static device scratch (no allocations allowed)
// ------------------------------------------------------------------
__device__ __align__(16) __half g_UThi[TLEN][K1PAD];      // A1 [t][k] fp16 hi
__device__ __align__(16) __half g_UTlo[TLEN][K1PAD];      //            fp16 lo
__device__ __align__(16) __half g_B1hi[2][K1PAD][NPH];    // B1 [k][n]
__device__ __align__(16) __half g_B1lo[2][K1PAD][NPH];
__device__ __align__(16) __half g_B2[2][K2PAD][NPH];      // B2 [k][n] single fp16
__device__ __align__(16) __half g_m1hi[2][TLEN][K2PAD];   // A2 [t][k]
__device__ __align__(16) __half g_m1lo[2][TLEN][K2PAD];
__device__ __align__(16) float g_PU[2][TLEN][NPH];        // fp32, 104 MB
__device__ __align__(16) float g_m2[2][TLEN][HD];
__device__ __align__(16) float g_b2T[2][NPH];
__device__ __align__(16) float g_prT[2][NPH];
__device__ float g_g[4 * HD];
__device__ float g_hB[2][HD];   // h parity buffers (state AFTER iter it at [it&1])
__device__ float g_cB[2][HD];
__device__ float g_r[2][HD];
__device__ unsigned long long g_slot[2][2];  // [parity][net] packed argmax

// ------------------------------------------------------------------
// helpers
// ------------------------------------------------------------------
__device__ __forceinline__ uint32_t smem_u32(const void* p) {
    uint32_t a;
    asm("{ .reg .u64 t; cvta.to.shared.u64 t, %1; cvt.u32.u64 %0, t; }" : "=r"(a) : "l"(p));
    return a;
}
__device__ __forceinline__ void cp16(uint32_t dst, const void* src) {
    asm volatile("cp.async.cg.shared.global [%0], [%1], 16;" :: "r"(dst), "l"(src));
}
#define CP_COMMIT() asm volatile("cp.async.commit_group;" ::: "memory")
#define CP_WAIT0()  asm volatile("cp.async.wait_group 0;" ::: "memory")

__device__ __forceinline__ void ldsm4(uint32_t* r, uint32_t addr) {
    asm volatile("ldmatrix.sync.aligned.m8n8.x4.shared.b16 {%0,%1,%2,%3}, [%4];"
                 : "=r"(r[0]), "=r"(r[1]), "=r"(r[2]), "=r"(r[3]) : "r"(addr));
}
__device__ __forceinline__ void ldsm4t(uint32_t* r, uint32_t addr) {
    asm volatile("ldmatrix.sync.aligned.m8n8.x4.trans.shared.b16 {%0,%1,%2,%3}, [%4];"
                 : "=r"(r[0]), "=r"(r[1]), "=r"(r[2]), "=r"(r[3]) : "r"(addr));
}
__device__ __forceinline__ void mma_f16(float* c, const uint32_t* a, const uint32_t* b) {
    asm volatile(
        "mma.sync.aligned.m16n8k16.row.col.f32.f16.f16.f32 "
        "{%0,%1,%2,%3}, {%4,%5,%6,%7}, {%8,%9}, {%0,%1,%2,%3};"
        : "+f"(c[0]), "+f"(c[1]), "+f"(c[2]), "+f"(c[3])
        : "r"(a[0]), "r"(a[1]), "r"(a[2]), "r"(a[3]), "r"(b[0]), "r"(b[1]));
}
__device__ __forceinline__ float sigm(float x) { return 1.0f / (1.0f + expf(-x)); }
__device__ __forceinline__ void split_f16(float v, __half& hi, __half& lo) {
    hi = __float2half(v);
    lo = __float2half(v - __half2float(hi));
}
__device__ __forceinline__ unsigned long long enc_max(float v, int t) {
    uint32_t u = __float_as_uint(v);
    u = (u & 0x80000000u) ? ~u : (u | 0x80000000u);
    return ((unsigned long long)u << 32) | (uint32_t)(TLEN - 1 - t);
}
__device__ __forceinline__ int dec_idx(unsigned long long s) {
    return TLEN - 1 - (int)(uint32_t)(s & 0xFFFFFFFFull);
}

// ------------------------------------------------------------------
// prep: build fp16 hi/lo operands + state reset (once per launch)
// ------------------------------------------------------------------
__global__ void prep_kernel(const float* __restrict__ W1a, const float* __restrict__ W1b,
                            const float* __restrict__ W2a, const float* __restrict__ W2b,
                            const float* __restrict__ b2a, const float* __restrict__ b2b,
                            const float* __restrict__ h0,  const float* __restrict__ c0,
                            const float* __restrict__ U) {
    int idx0 = blockIdx.x * blockDim.x + threadIdx.x;
    int stride = gridDim.x * blockDim.x;
    for (int i = idx0; i < TLEN * K1PAD; i += stride) {
        int t = i / K1PAD, k = i - t * K1PAD;
        float v = (k < 2 * HD) ? U[(size_t)k * TLEN + t] : 0.f;
        __half hi, lo; split_f16(v, hi, lo);
        g_UThi[t][k] = hi; g_UTlo[t][k] = lo;
    }
    for (int i = idx0; i < 2 * K1PAD * NPH; i += stride) {
        int net = i / (K1PAD * NPH);
        int rem = i - net * (K1PAD * NPH);
        int k = rem / NPH, n = rem - k * NPH;
        int h = n >> 4, p = n & 15;
        const float* W1 = net ? W1b : W1a;
        float v = (k < 2 * HD) ? W1[(size_t)(p * HD + h) * 600 + k] : 0.f;
        __half hi, lo; split_f16(v, hi, lo);
        g_B1hi[net][k][n] = hi; g_B1lo[net][k][n] = lo;
    }
    for (int i = idx0; i < 2 * K2PAD * NPH; i += stride) {
        int net = i / (K2PAD * NPH);
        int rem = i - net * (K2PAD * NPH);
        int k = rem / NPH, n = rem - k * NPH;
        int h = n >> 4, p = n & 15;
        const float* W2 = net ? W2b : W2a;
        float v = (k < HD) ? W2[(size_t)(p * HD + h) * HD + k] : 0.f;
        g_B2[net][k][n] = __float2half(v);
    }
    for (int i = idx0; i < 2 * NPH; i += stride) {
        int net = i / NPH, n = i - net * NPH;
        int h = n >> 4, p = n & 15;
        const float* b2 = net ? b2b : b2a;
        g_b2T[net][n] = b2[p * HD + h];
    }
    // zero m1 K pad (k in [200,224))
    for (int i = idx0; i < 2 * TLEN * (K2PAD - HD); i += stride) {
        int net = i / (TLEN * (K2PAD - HD));
        int rem = i - net * (TLEN * (K2PAD - HD));
        int t = rem / (K2PAD - HD);
        int k = HD + (rem - t * (K2PAD - HD));
        __half z = __float2half(0.f);
        g_m1hi[net][t][k] = z; g_m1lo[net][t][k] = z;
    }
    if (idx0 < HD) { g_hB[1][idx0] = h0[idx0]; g_cB[1][idx0] = c0[idx0]; }
}

// ------------------------------------------------------------------
// mma.sync GEMM: C[t][n] = sum_k A[t][k]*B[k][n]
// MODE 0: A=UT hi/lo, B=B1 hi/lo (3 MMAs) -> fp32 store to g_PU
// MODE 1: A=m1 hi/lo, B=B2 single (2 MMAs) -> +b2T, max over p -> g_m2
// Block tile 128(m) x 64(n), 256 threads, 8 warps (4m x 2n), K-chunk 32,
// 2-stage cp.async pipeline.
// ------------------------------------------------------------------
#define A_ROW_B   80
#define A_STG_B   10240
#define B_ROW_B   144
#define B_STG_B   4608
#define OFF_ALO   20480
#define OFF_BHI   40960
#define OFF_BLO   50176
#define GEMM_SMEM0 59392
#define GEMM_SMEM1 50176

template <int MODE>
__global__ void __launch_bounds__(256) gemm_mma() {
    extern __shared__ char smem[];
    const int tid    = threadIdx.x;
    const int lane   = tid & 31;
    const int wid    = tid >> 5;
    const int warp_m = wid & 3;
    const int warp_n = wid >> 2;
    const int net    = blockIdx.z;
    const int m0     = blockIdx.x * 128;
    const int n0     = blockIdx.y * 64;
    const int KPAD   = (MODE == 0) ? K1PAD : K2PAD;
    const int NC     = KPAD / 32;

    const __half* __restrict__ Ahi = (MODE == 0) ? &g_UThi[0][0] : &g_m1hi[net][0][0];
    const __half* __restrict__ Alo = (MODE == 0) ? &g_UTlo[0][0] : &g_m1lo[net][0][0];
    const __half* __restrict__ Bhi = (MODE == 0) ? &g_B1hi[net][0][0] : &g_B2[net][0][0];
    const __half* __restrict__ Blo = (MODE == 0) ? &g_B1lo[net][0][0] : (const __half*)0;

    const uint32_t sb = smem_u32(smem);

    const int arow = tid >> 1;
    const int aq   = (tid & 1) * 2;
    const int brow = tid >> 3;
    const int bq   = tid & 7;

    auto load_stage = [&](int stage, int kc) {
        const uint32_t as = sb + stage * A_STG_B + arow * A_ROW_B + aq * 16;
        const __half* ah = Ahi + (size_t)(m0 + arow) * KPAD + kc + aq * 8;
        const __half* al = Alo + (size_t)(m0 + arow) * KPAD + kc + aq * 8;
        cp16(as,                ah);
        cp16(as + 16,           ah + 8);
        cp16(as + OFF_ALO,      al);
        cp16(as + OFF_ALO + 16, al + 8);
        const uint32_t bs = sb + OFF_BHI + stage * B_STG_B + brow * B_ROW_B + bq * 16;
        const __half* bh = Bhi + (size_t)(kc + brow) * NPH + n0 + bq * 8;
        cp16(bs, bh);
        if (MODE == 0) {
            const __half* bl = Blo + (size_t)(kc + brow) * NPH + n0 + bq * 8;
            cp16(bs + (OFF_BLO - OFF_BHI), bl);
        }
    };

    float acc[2][4][4];
#pragma unroll
    for (int i = 0; i < 2; i++)
#pragma unroll
        for (int j = 0; j < 4; j++)
#pragma unroll
            for (int q = 0; q < 4; q++) acc[i][j][q] = 0.f;

    const int l15 = lane & 15;
    const int l16 = (lane >> 4) * 8;
    const uint32_t aBase = sb + (warp_m * 32 + l15) * A_ROW_B + l16 * 2;
    const uint32_t bBase = sb + OFF_BHI + l15 * B_ROW_B + (warp_n * 32 + l16) * 2;

    load_stage(0, 0);
    CP_COMMIT();

    for (int c = 0; c < NC; c++) {
        CP_WAIT0();
        __syncthreads();
        if (c + 1 < NC) { load_stage((c + 1) & 1, (c + 1) * 32); CP_COMMIT(); }
        const int stg = c & 1;
        const uint32_t aS = aBase + stg * A_STG_B;
        const uint32_t bS = bBase + stg * B_STG_B;
#pragma unroll
        for (int s = 0; s < 2; s++) {
            uint32_t ah[2][4], al[2][4], bh[4][2], bl[4][2];
#pragma unroll
            for (int i = 0; i < 2; i++) {
                uint32_t ao = aS + i * 16 * A_ROW_B + s * 32;
                ldsm4(ah[i], ao);
                ldsm4(al[i], ao + OFF_ALO);
            }
#pragma unroll
            for (int pr = 0; pr < 2; pr++) {
                uint32_t bo = bS + s * 16 * B_ROW_B + pr * 32;
                uint32_t r[4];
                ldsm4t(r, bo);
                bh[pr * 2][0] = r[0]; bh[pr * 2][1] = r[1];
                bh[pr * 2 + 1][0] = r[2]; bh[pr * 2 + 1][1] = r[3];
                if (MODE == 0) {
                    ldsm4t(r, bo + (OFF_BLO - OFF_BHI));
                    bl[pr * 2][0] = r[0]; bl[pr * 2][1] = r[1];
                    bl[pr * 2 + 1][0] = r[2]; bl[pr * 2 + 1][1] = r[3];
                }
            }
#pragma unroll
            for (int i = 0; i < 2; i++)
#pragma unroll
                for (int j = 0; j < 4; j++) {
                    mma_f16(acc[i][j], ah[i], bh[j]);
                    mma_f16(acc[i][j], al[i], bh[j]);
                    if (MODE == 0) mma_f16(acc[i][j], ah[i], bl[j]);
                }
        }
        __syncthreads();
    }

    const int g4 = lane >> 2;
    const int t2 = (lane & 3) * 2;
    if (MODE == 0) {
        float* C = &g_PU[net][0][0];
#pragma unroll
        for (int i = 0; i < 2; i++) {
            int r0 = m0 + warp_m * 32 + i * 16 + g4;
#pragma unroll
            for (int j = 0; j < 4; j++) {
                int col = n0 + warp_n * 32 + j * 8 + t2;
                *(float2*)&C[(size_t)r0 * NPH + col] =
                    make_float2(acc[i][j][0], acc[i][j][1]);
                *(float2*)&C[(size_t)(r0 + 8) * NPH + col] =
                    make_float2(acc[i][j][2], acc[i][j][3]);
            }
        }
    } else {
        float b2v[4][2];
#pragma unroll
        for (int j = 0; j < 4; j++) {
            int col = n0 + warp_n * 32 + j * 8 + t2;
            b2v[j][0] = __ldg(&g_b2T[net][col]);
            b2v[j][1] = __ldg(&g_b2T[net][col + 1]);
        }
        const int h0i = (n0 + warp_n * 32) >> 4;
#pragma unroll
        for (int i = 0; i < 2; i++) {
#pragma unroll
            for (int hh = 0; hh < 2; hh++) {
                float mx0 = -3.4e38f, mx1 = -3.4e38f;
#pragma unroll
                for (int j = 0; j < 4; j++) {
                    float v0 = acc[i][j][hh * 2]     + b2v[j][0];
                    float v1 = acc[i][j][hh * 2 + 1] + b2v[j][1];
                    float m = fmaxf(v0, v1);
                    if (j < 2) mx0 = fmaxf(mx0, m); else mx1 = fmaxf(mx1, m);
                }
                mx0 = fmaxf(mx0, __shfl_xor_sync(0xffffffffu, mx0, 1));
                mx0 = fmaxf(mx0, __shfl_xor_sync(0xffffffffu, mx0, 2));
                mx1 = fmaxf(mx1, __shfl_xor_sync(0xffffffffu, mx1, 1));
                mx1 = fmaxf(mx1, __shfl_xor_sync(0xffffffffu, mx1, 2));
                if ((lane & 3) == 0) {
                    int row = m0 + warp_m * 32 + i * 16 + hh * 8 + g4;
                    g_m2[net][row][h0i]     = mx0;
                    g_m2[net][row][h0i + 1] = mx1;
                }
            }
        }
    }
}

// ------------------------------------------------------------------
// LSTM gates: decodes s,e from slots, resets this-iter slots
// ------------------------------------------------------------------
__global__ void lstm_gates(const float* __restrict__ U, const float* __restrict__ W_ih,
                           const float* __restrict__ W_hh, const float* __restrict__ b_ih,
                           const float* __restrict__ b_hh, int it) {
    __shared__ float xs[800];
    __shared__ float hs[HD];
    int tid = threadIdx.x;
    int s = (it == 0) ? 0 : dec_idx(g_slot[(it + 1) & 1][0]);
    int e = (it == 0) ? 0 : dec_idx(g_slot[(it + 1) & 1][1]);
    if (blockIdx.x == 0 && tid == 0) {
        g_slot[it & 1][0] = 0ull;
        g_slot[it & 1][1] = 0ull;
    }
    for (int j = tid; j < 800; j += 256)
        xs[j] = (j < 400) ? U[(size_t)j * TLEN + s] : U[(size_t)(j - 400) * TLEN + e];
    const float* hprev = g_hB[(it + 1) & 1];
    for (int j = tid; j < HD; j += 256) hs[j] = hprev[j];
    __syncthreads();
    int row = blockIdx.x * 8 + (tid >> 5);
    int lane = tid & 31;
    const float* wr = &W_ih[(size_t)row * 800];
    float acc = 0.f;
    for (int k = lane; k < 800; k += 32) acc += wr[k] * xs[k];
    const float* wh = &W_hh[(size_t)row * HD];
    for (int k = lane; k < HD; k += 32) acc += wh[k] * hs[k];
#pragma unroll
    for (int o = 16; o; o >>= 1) acc += __shfl_xor_sync(0xffffffffu, acc, o);
    if (lane == 0) g_g[row] = acc + b_ih[row] + b_hh[row];
}

// ------------------------------------------------------------------
// fused LSTM update + r = tanh(WD @ [h_new, u_s, u_e]) for both nets
// each block recomputes h_new locally; block 0 persists h,c
// ------------------------------------------------------------------
__global__ void r_kernel(const float* __restrict__ U, const float* __restrict__ WDa,
                         const float* __restrict__ WDb, int it) {
    __shared__ float vs[1000];
    int tid = threadIdx.x;
    int s = (it == 0) ? 0 : dec_idx(g_slot[(it + 1) & 1][0]);
    int e = (it == 0) ? 0 : dec_idx(g_slot[(it + 1) & 1][1]);
    // recompute LSTM update locally (200 elems)
    if (tid < HD) {
        float gi = g_g[tid], gf = g_g[HD + tid], gg = g_g[2 * HD + tid], go = g_g[3 * HD + tid];
        float c = sigm(gf) * g_cB[(it + 1) & 1][tid] + sigm(gi) * tanhf(gg);
        float h = sigm(go) * tanhf(c);
        vs[tid] = h;
        if (blockIdx.x == 0) { g_cB[it & 1][tid] = c; g_hB[it & 1][tid] = h; }
    }
    for (int j = tid; j < 800; j += 256) {
        int jj = HD + j;
        vs[jj] = (j < 400) ? U[(size_t)j * TLEN + s] : U[(size_t)(j - 400) * TLEN + e];
    }
    __syncthreads();
    int row = blockIdx.x * 8 + (tid >> 5);
    int lane = tid & 31;
    int net = row / HD;
    int rr = row - net * HD;
    const float* WD = net ? WDb : WDa;
    const float* wr = &WD[(size_t)rr * 1000];
    float acc = 0.f;
    for (int k = lane; k < 1000; k += 32) acc += wr[k] * vs[k];
#pragma unroll
    for (int o = 16; o; o >>= 1) acc += __shfl_xor_sync(0xffffffffu, acc, o);
    if (lane == 0) g_r[net][rr] = tanhf(acc);
}

// ------------------------------------------------------------------
// prT[net][h*16+p] = W1r[p][h]@r + b1[p][h]
// ------------------------------------------------------------------
__global__ void pr_kernel(const float* __restrict__ W1a, const float* __restrict__ W1b,
                          const float* __restrict__ b1a, const float* __restrict__ b1b) {
    int o = blockIdx.x * 8 + (threadIdx.x >> 5);
    int lane = threadIdx.x & 31;
    int net = o / NPH;
    int n = o - net * NPH;
    int h = n >> 4, p = n & 15;
    const float* W1 = net ? W1b : W1a;
    const float* b1 = net ? b1b : b1a;
    const float* w = &W1[(size_t)(p * HD + h) * 600 + 400];
    const float* r = g_r[net];
    float acc = 0.f;
    for (int k = lane; k < HD; k += 32) acc += w[k] * r[k];
#pragma unroll
    for (int o2 = 16; o2; o2 >>= 1) acc += __shfl_xor_sync(0xffffffffu, acc, o2);
    if (lane == 0) g_prT[net][n] = acc + b1[p * HD + h];
}

// ------------------------------------------------------------------
// m1[t][h] = max_p(PU[t][h*16+p] + prT[h*16+p]) -> fp16 hi/lo
// ------------------------------------------------------------------
__global__ void m1_kernel() {
    int t = blockIdx.x, net = blockIdx.y;
    int h = threadIdx.x;
    if (h >= HD) return;
    const float4* pu = (const float4*)&g_PU[net][t][h << 4];
    const float4* pr = (const float4*)&g_prT[net][h << 4];
    float m = -3.4e38f;
#pragma unroll
    for (int q = 0; q < 4; q++) {
        float4 a = pu[q], b = pr[q];
        m = fmaxf(m, fmaxf(fmaxf(a.x + b.x, a.y + b.y), fmaxf(a.z + b.z, a.w + b.w)));
    }
    __half hi, lo; split_f16(m, hi, lo);
    g_m1hi[net][t][h] = hi;
    g_m1lo[net][t][h] = lo;
}

// ------------------------------------------------------------------
// scores + fused argmax: alpha[t] = max_p([m1,m2].W3[p] + b3[p])
// 512 threads, 32 t per block; one atomicMax per block per net
// ------------------------------------------------------------------
#define SCORE_SMEM ((32 * 408 + 16 * 401 + 64) * 4)
__global__ void __launch_bounds__(512) score_kernel(
        const float* __restrict__ W3a, const float* __restrict__ W3b,
        const float* __restrict__ b3a, const float* __restrict__ b3b,
        float* __restrict__ out, int it, int maxI) {
    extern __shared__ float sm[];
    float* ms  = sm;                 // [32][408]
    float* w3s = sm + 32 * 408;      // [16][401]
    float* bmx = w3s + 16 * 401;     // [32] block max vals
    int*   bmi = (int*)(bmx + 32);   // [32] t indices
    int net = blockIdx.y;
    int t0 = blockIdx.x * 32;
    int tid = threadIdx.x;
    const float* W3 = net ? W3b : W3a;
    for (int idx = tid; idx < 6400; idx += 512) {
        int p = idx / 400, d = idx - p * 400;
        w3s[p * 401 + d] = W3[p * 400 + d];
    }
    for (int idx = tid; idx < 32 * HD; idx += 512) {
        int tt = idx / HD, h = idx - tt * HD;
        int t = t0 + tt;
        ms[tt * 408 + h] = __half2float(g_m1hi[net][t][h]) + __half2float(g_m1lo[net][t][h]);
        ms[tt * 408 + 200 + h] = g_m2[net][t][h];
    }
    __syncthreads();
    int tt = tid >> 4, p = tid & 15;
    float acc = (net ? b3b : b3a)[p];
    const float* msr = &ms[tt * 408];
    const float* w3r = &w3s[p * 401];
#pragma unroll 4
    for (int d = 0; d < 400; d++) acc = fmaf(msr[d], w3r[d], acc);
#pragma unroll
    for (int o = 8; o; o >>= 1) acc = fmaxf(acc, __shfl_xor_sync(0xffffffffu, acc, o));
    if (p == 0) {
        out[((size_t)net * maxI + it) * TLEN + t0 + tt] = acc;
        bmx[tt] = acc;
        bmi[tt] = t0 + tt;
    }
    __syncthreads();
    if (tid == 0) {
        float bv = bmx[0]; int bi = bmi[0];
        for (int q = 1; q < 32; q++) {
            if (bmx[q] > bv) { bv = bmx[q]; bi = bmi[q]; }
        }
        atomicMax(&g_slot[it & 1][net], enc_max(bv, bi));
    }
}

// ------------------------------------------------------------------
// finalize: write s,e
// ------------------------------------------------------------------
__global__ void finalize_kernel(float* __restrict__ out, int maxI) {
    out[(size_t)2 * maxI * TLEN + 0] = (float)dec_idx(g_slot[(maxI - 1) & 1][0]);
    out[(size_t)2 * maxI * TLEN + 1] = (float)dec_idx(g_slot[(maxI - 1) & 1][1]);
}

// ------------------------------------------------------------------
// launch
// ------------------------------------------------------------------
extern "C" void kernel_launch(void* const* d_in, const int* in_sizes, int n_in,
                              void* d_out, int out_size) {
    const float* U    = (const float*)d_in[0];
    const float* h0   = (const float*)d_in[2];
    const float* c0   = (const float*)d_in[3];
    const float* W_ih = (const float*)d_in[4];
    const float* W_hh = (const float*)d_in[5];
    const float* b_ih = (const float*)d_in[6];
    const float* b_hh = (const float*)d_in[7];
    const float* WD_a = (const float*)d_in[8];
    const float* W1_a = (const float*)d_in[9];
    const float* b1_a = (const float*)d_in[10];
    const float* W2_a = (const float*)d_in[11];
    const float* b2_a = (const float*)d_in[12];
    const float* W3_a = (const float*)d_in[13];
    const float* b3_a = (const float*)d_in[14];
    const float* WD_b = (const float*)d_in[15];
    const float* W1_b = (const float*)d_in[16];
    const float* b1_b = (const float*)d_in[17];
    const float* W2_b = (const float*)d_in[18];
    const float* b2_b = (const float*)d_in[19];
    const float* W3_b = (const float*)d_in[20];
    const float* b3_b = (const float*)d_in[21];
    float* out = (float*)d_out;

    int maxI = out_size / (2 * TLEN);
    if (maxI < 1) maxI = 1;
    int write_se = (out_size >= 2 * maxI * TLEN + 2) ? 1 : 0;

    cudaFuncSetAttribute(gemm_mma<0>, cudaFuncAttributeMaxDynamicSharedMemorySize, GEMM_SMEM0);
    cudaFuncSetAttribute(gemm_mma<1>, cudaFuncAttributeMaxDynamicSharedMemorySize, GEMM_SMEM1);
    cudaFuncSetAttribute(score_kernel, cudaFuncAttributeMaxDynamicSharedMemorySize, SCORE_SMEM);

    prep_kernel<<<2048, 256>>>(W1_a, W1_b, W2_a, W2_b, b2_a, b2_b, h0, c0, U);
    gemm_mma<0><<<dim3(TLEN / 128, NPH / 64, 2), 256, GEMM_SMEM0>>>();

    for (int it = 0; it < maxI; it++) {
        lstm_gates<<<100, 256>>>(U, W_ih, W_hh, b_ih, b_hh, it);
        r_kernel<<<50, 256>>>(U, WD_a, WD_b, it);
        pr_kernel<<<800, 256>>>(W1_a, W1_b, b1_a, b1_b);
        m1_kernel<<<dim3(TLEN, 2), 256>>>();
        gemm_mma<1><<<dim3(TLEN / 128, NPH / 64, 2), 256, GEMM_SMEM1>>>();
        score_kernel<<<dim3(TLEN / 32, 2), 512, SCORE_SMEM>>>(W3_a, W3_b, b3_a, b3_b, out, it, maxI);
    }
    if (write_se) finalize_kernel<<<1, 1>>>(out, maxI);
}

// round 5
// speedup vs baseline: 3.3663x; 1.1150x over previous
#include <cuda_runtime.h>
#include <cuda_fp16.h>
#include <math.h>
#include <stdint.h>

#define HD    200
#define POOL  16
#define TLEN  4096
#define NPH   3200   // POOL*HD
#define K1PAD 416    // pad of 2*HD=400 to mult of 32
#define K2PAD 224    // pad of HD=200 to mult of 32

// ------------------------------------------------------------------
// Static device scratch
// ------------------------------------------------------------------
__device__ __align__(16) __half g_UThi[TLEN][K1PAD];      // A1 [t][k]
__device__ __align__(16) __half g_UTlo[TLEN][K1PAD];
__device__ __align__(16) __half g_B1[2][K1PAD][NPH];      // B1 [k][n] single fp16
__device__ __align__(16) __half g_B2[2][K2PAD][NPH];      // B2 [k][n] single fp16
__device__ __align__(16) __half g_m1hi[2][TLEN][K2PAD];   // A2 [t][k]
__device__ __align__(16) __half g_m1lo[2][TLEN][K2PAD];
__device__ __align__(16) float g_PU[2][TLEN][NPH];        // fp32, 104 MB
__device__ __align__(16) float g_m2[2][TLEN][HD];
__device__ __align__(16) float g_b2T[2][NPH];
__device__ __align__(16) float g_prT[2][NPH];
__device__ float g_g[4 * HD];
__device__ float g_hB[2][HD];
__device__ float g_cB[2][HD];
__device__ float g_r[2][HD];
__device__ unsigned long long g_slot[2][2];

// ------------------------------------------------------------------
// helpers
// ------------------------------------------------------------------
__device__ __forceinline__ uint32_t smem_u32(const void* p) {
    uint32_t a;
    asm("{ .reg .u64 t; cvta.to.shared.u64 t, %1; cvt.u32.u64 %0, t; }" : "=r"(a) : "l"(p));
    return a;
}
__device__ __forceinline__ void cp16(uint32_t dst, const void* src) {
    asm volatile("cp.async.cg.shared.global [%0], [%1], 16;" :: "r"(dst), "l"(src));
}
#define CP_COMMIT() asm volatile("cp.async.commit_group;" ::: "memory")
#define CP_WAIT0()  asm volatile("cp.async.wait_group 0;" ::: "memory")

__device__ __forceinline__ void ldsm4(uint32_t* r, uint32_t addr) {
    asm volatile("ldmatrix.sync.aligned.m8n8.x4.shared.b16 {%0,%1,%2,%3}, [%4];"
                 : "=r"(r[0]), "=r"(r[1]), "=r"(r[2]), "=r"(r[3]) : "r"(addr));
}
__device__ __forceinline__ void ldsm4t(uint32_t* r, uint32_t addr) {
    asm volatile("ldmatrix.sync.aligned.m8n8.x4.trans.shared.b16 {%0,%1,%2,%3}, [%4];"
                 : "=r"(r[0]), "=r"(r[1]), "=r"(r[2]), "=r"(r[3]) : "r"(addr));
}
__device__ __forceinline__ void mma_f16(float* c, const uint32_t* a, const uint32_t* b) {
    asm volatile(
        "mma.sync.aligned.m16n8k16.row.col.f32.f16.f16.f32 "
        "{%0,%1,%2,%3}, {%4,%5,%6,%7}, {%8,%9}, {%0,%1,%2,%3};"
        : "+f"(c[0]), "+f"(c[1]), "+f"(c[2]), "+f"(c[3])
        : "r"(a[0]), "r"(a[1]), "r"(a[2]), "r"(a[3]), "r"(b[0]), "r"(b[1]));
}
__device__ __forceinline__ float sigm(float x) { return 1.0f / (1.0f + expf(-x)); }
__device__ __forceinline__ void split_f16(float v, __half& hi, __half& lo) {
    hi = __float2half(v);
    lo = __float2half(v - __half2float(hi));
}
__device__ __forceinline__ unsigned long long enc_max(float v, int t) {
    uint32_t u = __float_as_uint(v);
    u = (u & 0x80000000u) ? ~u : (u | 0x80000000u);
    return ((unsigned long long)u << 32) | (uint32_t)(TLEN - 1 - t);
}
__device__ __forceinline__ int dec_idx(unsigned long long s) {
    return TLEN - 1 - (int)(uint32_t)(s & 0xFFFFFFFFull);
}

// ------------------------------------------------------------------
// prep
// ------------------------------------------------------------------
__global__ void prep_kernel(const float* __restrict__ W1a, const float* __restrict__ W1b,
                            const float* __restrict__ W2a, const float* __restrict__ W2b,
                            const float* __restrict__ b2a, const float* __restrict__ b2b,
                            const float* __restrict__ h0,  const float* __restrict__ c0,
                            const float* __restrict__ U) {
    int idx0 = blockIdx.x * blockDim.x + threadIdx.x;
    int stride = gridDim.x * blockDim.x;
    for (int i = idx0; i < TLEN * K1PAD; i += stride) {
        int t = i / K1PAD, k = i - t * K1PAD;
        float v = (k < 2 * HD) ? U[(size_t)k * TLEN + t] : 0.f;
        __half hi, lo; split_f16(v, hi, lo);
        g_UThi[t][k] = hi; g_UTlo[t][k] = lo;
    }
    for (int i = idx0; i < 2 * K1PAD * NPH; i += stride) {
        int net = i / (K1PAD * NPH);
        int rem = i - net * (K1PAD * NPH);
        int k = rem / NPH, n = rem - k * NPH;
        int h = n >> 4, p = n & 15;
        const float* W1 = net ? W1b : W1a;
        float v = (k < 2 * HD) ? W1[(size_t)(p * HD + h) * 600 + k] : 0.f;
        g_B1[net][k][n] = __float2half(v);
    }
    for (int i = idx0; i < 2 * K2PAD * NPH; i += stride) {
        int net = i / (K2PAD * NPH);
        int rem = i - net * (K2PAD * NPH);
        int k = rem / NPH, n = rem - k * NPH;
        int h = n >> 4, p = n & 15;
        const float* W2 = net ? W2b : W2a;
        float v = (k < HD) ? W2[(size_t)(p * HD + h) * HD + k] : 0.f;
        g_B2[net][k][n] = __float2half(v);
    }
    for (int i = idx0; i < 2 * NPH; i += stride) {
        int net = i / NPH, n = i - net * NPH;
        int h = n >> 4, p = n & 15;
        const float* b2 = net ? b2b : b2a;
        g_b2T[net][n] = b2[p * HD + h];
    }
    for (int i = idx0; i < 2 * TLEN * (K2PAD - HD); i += stride) {
        int net = i / (TLEN * (K2PAD - HD));
        int rem = i - net * (TLEN * (K2PAD - HD));
        int t = rem / (K2PAD - HD);
        int k = HD + (rem - t * (K2PAD - HD));
        __half z = __float2half(0.f);
        g_m1hi[net][t][k] = z; g_m1lo[net][t][k] = z;
    }
    if (idx0 < HD) { g_hB[1][idx0] = h0[idx0]; g_cB[1][idx0] = c0[idx0]; }
}

// ------------------------------------------------------------------
// mma.sync GEMM: C[t][n] = sum_k A[t][k]*B[k][n]; A = hi/lo fp16 (exact),
// B = single fp16.  2 MMAs per tile.
// MODE 0: A=UT (K=416), B=B1 -> fp32 store to g_PU
// MODE 1: A=m1 (K=224), B=B2 -> +b2T, max over p -> g_m2[t][h]
// Block tile 128(m) x 128(n), 256 threads, 8 warps (4m x 2n), warp 32x64,
// K-chunk 32, 2-stage cp.async pipeline.
// ------------------------------------------------------------------
#define A_ROW_B   80
#define A_STG_B   10240
#define OFF_ALO   20480
#define OFF_B     40960
#define B_ROW_B   272
#define B_STG_B   8704
#define GEMM_SMEM 58368

template <int MODE>
__global__ void __launch_bounds__(256) gemm_mma() {
    extern __shared__ char smem[];
    const int tid    = threadIdx.x;
    const int lane   = tid & 31;
    const int wid    = tid >> 5;
    const int warp_m = wid & 3;
    const int warp_n = wid >> 2;
    const int net    = blockIdx.z;
    const int m0     = blockIdx.x * 128;
    const int n0     = blockIdx.y * 128;
    const int KPAD   = (MODE == 0) ? K1PAD : K2PAD;
    const int NC     = KPAD / 32;

    const __half* __restrict__ Ahi = (MODE == 0) ? &g_UThi[0][0] : &g_m1hi[net][0][0];
    const __half* __restrict__ Alo = (MODE == 0) ? &g_UTlo[0][0] : &g_m1lo[net][0][0];
    const __half* __restrict__ Bp  = (MODE == 0) ? &g_B1[net][0][0] : &g_B2[net][0][0];

    const uint32_t sb = smem_u32(smem);

    const int arow = tid >> 1;
    const int aq   = (tid & 1) * 2;
    const int brow = tid >> 3;
    const int bq   = tid & 7;

    auto load_stage = [&](int stage, int kc) {
        const uint32_t as = sb + stage * A_STG_B + arow * A_ROW_B + aq * 16;
        const __half* ah = Ahi + (size_t)(m0 + arow) * KPAD + kc + aq * 8;
        const __half* al = Alo + (size_t)(m0 + arow) * KPAD + kc + aq * 8;
        cp16(as,                ah);
        cp16(as + 16,           ah + 8);
        cp16(as + OFF_ALO,      al);
        cp16(as + OFF_ALO + 16, al + 8);
        const uint32_t bs = sb + OFF_B + stage * B_STG_B + brow * B_ROW_B + bq * 32;
        const __half* bg = Bp + (size_t)(kc + brow) * NPH + n0 + bq * 16;
        cp16(bs,      bg);
        cp16(bs + 16, bg + 8);
    };

    float acc[2][8][4];
#pragma unroll
    for (int i = 0; i < 2; i++)
#pragma unroll
        for (int j = 0; j < 8; j++)
#pragma unroll
            for (int q = 0; q < 4; q++) acc[i][j][q] = 0.f;

    const int l15 = lane & 15;
    const int l16 = (lane >> 4) * 8;
    const uint32_t aBase = sb + (warp_m * 32 + l15) * A_ROW_B + l16 * 2;
    const uint32_t bBase = sb + OFF_B + l15 * B_ROW_B + (warp_n * 64 + l16) * 2;

    load_stage(0, 0);
    CP_COMMIT();

    for (int c = 0; c < NC; c++) {
        CP_WAIT0();
        __syncthreads();
        if (c + 1 < NC) { load_stage((c + 1) & 1, (c + 1) * 32); CP_COMMIT(); }
        const int stg = c & 1;
        const uint32_t aS = aBase + stg * A_STG_B;
        const uint32_t bS = bBase + stg * B_STG_B;
#pragma unroll
        for (int s = 0; s < 2; s++) {
            uint32_t ah[2][4], al[2][4];
#pragma unroll
            for (int i = 0; i < 2; i++) {
                uint32_t ao = aS + i * 16 * A_ROW_B + s * 32;
                ldsm4(ah[i], ao);
                ldsm4(al[i], ao + OFF_ALO);
            }
#pragma unroll
            for (int half = 0; half < 2; half++) {
                uint32_t bb[4][2];
#pragma unroll
                for (int pr = 0; pr < 2; pr++) {
                    uint32_t r[4];
                    ldsm4t(r, bS + s * 16 * B_ROW_B + (half * 2 + pr) * 32);
                    bb[pr * 2][0] = r[0]; bb[pr * 2][1] = r[1];
                    bb[pr * 2 + 1][0] = r[2]; bb[pr * 2 + 1][1] = r[3];
                }
#pragma unroll
                for (int i = 0; i < 2; i++)
#pragma unroll
                    for (int j = 0; j < 4; j++) {
                        mma_f16(acc[i][half * 4 + j], ah[i], bb[j]);
                        mma_f16(acc[i][half * 4 + j], al[i], bb[j]);
                    }
            }
        }
        __syncthreads();
    }

    const int g4 = lane >> 2;
    const int t2 = (lane & 3) * 2;
    if (MODE == 0) {
        float* C = &g_PU[net][0][0];
#pragma unroll
        for (int i = 0; i < 2; i++) {
            int r0 = m0 + warp_m * 32 + i * 16 + g4;
#pragma unroll
            for (int j = 0; j < 8; j++) {
                int col = n0 + warp_n * 64 + j * 8 + t2;
                *(float2*)&C[(size_t)r0 * NPH + col] =
                    make_float2(acc[i][j][0], acc[i][j][1]);
                *(float2*)&C[(size_t)(r0 + 8) * NPH + col] =
                    make_float2(acc[i][j][2], acc[i][j][3]);
            }
        }
    } else {
        float b2v[8][2];
#pragma unroll
        for (int j = 0; j < 8; j++) {
            int col = n0 + warp_n * 64 + j * 8 + t2;
            b2v[j][0] = __ldg(&g_b2T[net][col]);
            b2v[j][1] = __ldg(&g_b2T[net][col + 1]);
        }
        const int h0i = (n0 + warp_n * 64) >> 4;
#pragma unroll
        for (int i = 0; i < 2; i++) {
#pragma unroll
            for (int hh = 0; hh < 4; hh++) {
                float mlo = -3.4e38f, mhi = -3.4e38f;
#pragma unroll
                for (int jj = 0; jj < 2; jj++) {
                    int j = hh * 2 + jj;
                    mlo = fmaxf(mlo, fmaxf(acc[i][j][0] + b2v[j][0], acc[i][j][1] + b2v[j][1]));
                    mhi = fmaxf(mhi, fmaxf(acc[i][j][2] + b2v[j][0], acc[i][j][3] + b2v[j][1]));
                }
                mlo = fmaxf(mlo, __shfl_xor_sync(0xffffffffu, mlo, 1));
                mlo = fmaxf(mlo, __shfl_xor_sync(0xffffffffu, mlo, 2));
                mhi = fmaxf(mhi, __shfl_xor_sync(0xffffffffu, mhi, 1));
                mhi = fmaxf(mhi, __shfl_xor_sync(0xffffffffu, mhi, 2));
                if ((lane & 3) == 0) {
                    int row = m0 + warp_m * 32 + i * 16 + g4;
                    g_m2[net][row][h0i + hh]     = mlo;
                    g_m2[net][row + 8][h0i + hh] = mhi;
                }
            }
        }
    }
}

// ------------------------------------------------------------------
// LSTM gates: 4 rows/block, 2 warps per row
// ------------------------------------------------------------------
__global__ void lstm_gates(const float* __restrict__ U, const float* __restrict__ W_ih,
                           const float* __restrict__ W_hh, const float* __restrict__ b_ih,
                           const float* __restrict__ b_hh, int it) {
    __shared__ float xs[800];
    __shared__ float hs[HD];
    __shared__ float wsum[8];
    int tid = threadIdx.x;
    int s = (it == 0) ? 0 : dec_idx(g_slot[(it + 1) & 1][0]);
    int e = (it == 0) ? 0 : dec_idx(g_slot[(it + 1) & 1][1]);
    if (blockIdx.x == 0 && tid == 0) {
        g_slot[it & 1][0] = 0ull;
        g_slot[it & 1][1] = 0ull;
    }
    for (int j = tid; j < 800; j += 256)
        xs[j] = (j < 400) ? U[(size_t)j * TLEN + s] : U[(size_t)(j - 400) * TLEN + e];
    const float* hprev = g_hB[(it + 1) & 1];
    for (int j = tid; j < HD; j += 256) hs[j] = hprev[j];
    __syncthreads();
    int row = blockIdx.x * 4 + (tid >> 6);
    int l64 = tid & 63;
    int lane = tid & 31;
    const float* wr = &W_ih[(size_t)row * 800];
    float acc = 0.f;
    for (int k = l64; k < 800; k += 64) acc += wr[k] * xs[k];
    const float* wh = &W_hh[(size_t)row * HD];
    for (int k = l64; k < HD; k += 64) acc += wh[k] * hs[k];
#pragma unroll
    for (int o = 16; o; o >>= 1) acc += __shfl_xor_sync(0xffffffffu, acc, o);
    if (lane == 0) wsum[tid >> 5] = acc;
    __syncthreads();
    if (l64 == 0) {
        int w = tid >> 5;
        g_g[row] = wsum[w] + wsum[w + 1] + b_ih[row] + b_hh[row];
    }
}

// ------------------------------------------------------------------
// fused LSTM update + r = tanh(WD @ [h_new, u_s, u_e]); 4 rows/block
// ------------------------------------------------------------------
__global__ void r_kernel(const float* __restrict__ U, const float* __restrict__ WDa,
                         const float* __restrict__ WDb, int it) {
    __shared__ float vs[1000];
    __shared__ float wsum[8];
    int tid = threadIdx.x;
    int s = (it == 0) ? 0 : dec_idx(g_slot[(it + 1) & 1][0]);
    int e = (it == 0) ? 0 : dec_idx(g_slot[(it + 1) & 1][1]);
    if (tid < HD) {
        float gi = g_g[tid], gf = g_g[HD + tid], gg = g_g[2 * HD + tid], go = g_g[3 * HD + tid];
        float c = sigm(gf) * g_cB[(it + 1) & 1][tid] + sigm(gi) * tanhf(gg);
        float h = sigm(go) * tanhf(c);
        vs[tid] = h;
        if (blockIdx.x == 0) { g_cB[it & 1][tid] = c; g_hB[it & 1][tid] = h; }
    }
    for (int j = tid; j < 800; j += 256) {
        int jj = HD + j;
        vs[jj] = (j < 400) ? U[(size_t)j * TLEN + s] : U[(size_t)(j - 400) * TLEN + e];
    }
    __syncthreads();
    int row = blockIdx.x * 4 + (tid >> 6);
    int l64 = tid & 63;
    int lane = tid & 31;
    int net = row / HD;
    int rr = row - net * HD;
    const float* WD = net ? WDb : WDa;
    const float* wr = &WD[(size_t)rr * 1000];
    float acc = 0.f;
    for (int k = l64; k < 1000; k += 64) acc += wr[k] * vs[k];
#pragma unroll
    for (int o = 16; o; o >>= 1) acc += __shfl_xor_sync(0xffffffffu, acc, o);
    if (lane == 0) wsum[tid >> 5] = acc;
    __syncthreads();
    if (l64 == 0) {
        int w = tid >> 5;
        g_r[net][rr] = tanhf(wsum[w] + wsum[w + 1]);
    }
}

// ------------------------------------------------------------------
// prT[net][h*16+p] = W1r[p][h]@r + b1[p][h]
// ------------------------------------------------------------------
__global__ void pr_kernel(const float* __restrict__ W1a, const float* __restrict__ W1b,
                          const float* __restrict__ b1a, const float* __restrict__ b1b) {
    int o = blockIdx.x * 8 + (threadIdx.x >> 5);
    int lane = threadIdx.x & 31;
    int net = o / NPH;
    int n = o - net * NPH;
    int h = n >> 4, p = n & 15;
    const float* W1 = net ? W1b : W1a;
    const float* b1 = net ? b1b : b1a;
    const float* w = &W1[(size_t)(p * HD + h) * 600 + 400];
    const float* r = g_r[net];
    float acc = 0.f;
    for (int k = lane; k < HD; k += 32) acc += w[k] * r[k];
#pragma unroll
    for (int o2 = 16; o2; o2 >>= 1) acc += __shfl_xor_sync(0xffffffffu, acc, o2);
    if (lane == 0) g_prT[net][n] = acc + b1[p * HD + h];
}

// ------------------------------------------------------------------
// m1[t][h] = max_p(PU[t][h*16+p] + prT[h*16+p]) -> fp16 hi/lo
// ------------------------------------------------------------------
__global__ void m1_kernel() {
    int t = blockIdx.x, net = blockIdx.y;
    int h = threadIdx.x;
    if (h >= HD) return;
    const float4* pu = (const float4*)&g_PU[net][t][h << 4];
    const float4* pr = (const float4*)&g_prT[net][h << 4];
    float m = -3.4e38f;
#pragma unroll
    for (int q = 0; q < 4; q++) {
        float4 a = pu[q], b = pr[q];
        m = fmaxf(m, fmaxf(fmaxf(a.x + b.x, a.y + b.y), fmaxf(a.z + b.z, a.w + b.w)));
    }
    __half hi, lo; split_f16(m, hi, lo);
    g_m1hi[net][t][h] = hi;
    g_m1lo[net][t][h] = lo;
}

// ------------------------------------------------------------------
// scores + fused argmax
// ------------------------------------------------------------------
#define SCORE_SMEM ((32 * 408 + 16 * 401 + 64) * 4)
__global__ void __launch_bounds__(512) score_kernel(
        const float* __restrict__ W3a, const float* __restrict__ W3b,
        const float* __restrict__ b3a, const float* __restrict__ b3b,
        float* __restrict__ out, int it, int maxI) {
    extern __shared__ float sm[];
    float* ms  = sm;
    float* w3s = sm + 32 * 408;
    float* bmx = w3s + 16 * 401;
    int*   bmi = (int*)(bmx + 32);
    int net = blockIdx.y;
    int t0 = blockIdx.x * 32;
    int tid = threadIdx.x;
    const float* W3 = net ? W3b : W3a;
    for (int idx = tid; idx < 6400; idx += 512) {
        int p = idx / 400, d = idx - p * 400;
        w3s[p * 401 + d] = W3[p * 400 + d];
    }
    for (int idx = tid; idx < 32 * HD; idx += 512) {
        int tt = idx / HD, h = idx - tt * HD;
        int t = t0 + tt;
        ms[tt * 408 + h] = __half2float(g_m1hi[net][t][h]) + __half2float(g_m1lo[net][t][h]);
        ms[tt * 408 + 200 + h] = g_m2[net][t][h];
    }
    __syncthreads();
    int tt = tid >> 4, p = tid & 15;
    float acc = (net ? b3b : b3a)[p];
    const float* msr = &ms[tt * 408];
    const float* w3r = &w3s[p * 401];
#pragma unroll 4
    for (int d = 0; d < 400; d++) acc = fmaf(msr[d], w3r[d], acc);
#pragma unroll
    for (int o = 8; o; o >>= 1) acc = fmaxf(acc, __shfl_xor_sync(0xffffffffu, acc, o));
    if (p == 0) {
        out[((size_t)net * maxI + it) * TLEN + t0 + tt] = acc;
        bmx[tt] = acc;
        bmi[tt] = t0 + tt;
    }
    __syncthreads();
    if (tid == 0) {
        float bv = bmx[0]; int bi = bmi[0];
        for (int q = 1; q < 32; q++) {
            if (bmx[q] > bv) { bv = bmx[q]; bi = bmi[q]; }
        }
        atomicMax(&g_slot[it & 1][net], enc_max(bv, bi));
    }
}

__global__ void finalize_kernel(float* __restrict__ out, int maxI) {
    out[(size_t)2 * maxI * TLEN + 0] = (float)dec_idx(g_slot[(maxI - 1) & 1][0]);
    out[(size_t)2 * maxI * TLEN + 1] = (float)dec_idx(g_slot[(maxI - 1) & 1][1]);
}

// ------------------------------------------------------------------
// launch
// ------------------------------------------------------------------
extern "C" void kernel_launch(void* const* d_in, const int* in_sizes, int n_in,
                              void* d_out, int out_size) {
    const float* U    = (const float*)d_in[0];
    const float* h0   = (const float*)d_in[2];
    const float* c0   = (const float*)d_in[3];
    const float* W_ih = (const float*)d_in[4];
    const float* W_hh = (const float*)d_in[5];
    const float* b_ih = (const float*)d_in[6];
    const float* b_hh = (const float*)d_in[7];
    const float* WD_a = (const float*)d_in[8];
    const float* W1_a = (const float*)d_in[9];
    const float* b1_a = (const float*)d_in[10];
    const float* W2_a = (const float*)d_in[11];
    const float* b2_a = (const float*)d_in[12];
    const float* W3_a = (const float*)d_in[13];
    const float* b3_a = (const float*)d_in[14];
    const float* WD_b = (const float*)d_in[15];
    const float* W1_b = (const float*)d_in[16];
    const float* b1_b = (const float*)d_in[17];
    const float* W2_b = (const float*)d_in[18];
    const float* b2_b = (const float*)d_in[19];
    const float* W3_b = (const float*)d_in[20];
    const float* b3_b = (const float*)d_in[21];
    float* out = (float*)d_out;

    int maxI = out_size / (2 * TLEN);
    if (maxI < 1) maxI = 1;
    int write_se = (out_size >= 2 * maxI * TLEN + 2) ? 1 : 0;

    cudaFuncSetAttribute(gemm_mma<0>, cudaFuncAttributeMaxDynamicSharedMemorySize, GEMM_SMEM);
    cudaFuncSetAttribute(gemm_mma<1>, cudaFuncAttributeMaxDynamicSharedMemorySize, GEMM_SMEM);
    cudaFuncSetAttribute(score_kernel, cudaFuncAttributeMaxDynamicSharedMemorySize, SCORE_SMEM);

    prep_kernel<<<2048, 256>>>(W1_a, W1_b, W2_a, W2_b, b2_a, b2_b, h0, c0, U);
    gemm_mma<0><<<dim3(TLEN / 128, NPH / 128, 2), 256, GEMM_SMEM>>>();

    for (int it = 0; it < maxI; it++) {
        lstm_gates<<<200, 256>>>(U, W_ih, W_hh, b_ih, b_hh, it);
        r_kernel<<<100, 256>>>(U, WD_a, WD_b, it);
        pr_kernel<<<800, 256>>>(W1_a, W1_b, b1_a, b1_b);
        m1_kernel<<<dim3(TLEN, 2), 256>>>();
        gemm_mma<1><<<dim3(TLEN / 128, NPH / 128, 2), 256, GEMM_SMEM>>>();
        score_kernel<<<dim3(TLEN / 32, 2), 512, SCORE_SMEM>>>(W3_a, W3_b, b3_a, b3_b, out, it, maxI);
    }
    if (write_se) finalize_kernel<<<1, 1>>>(out, maxI);
}

// round 8
// speedup vs baseline: 4.4590x; 1.3246x over previous
#include <cuda_runtime.h>
#include <cuda_fp16.h>
#include <math.h>
#include <stdint.h>

#define HD    200
#define POOL  16
#define TLEN  4096
#define NPH   3200   // POOL*HD
#define K1PAD 416    // pad of 2*HD=400 to mult of 32
#define K2PAD 224    // pad of HD=200 to mult of 32

// ------------------------------------------------------------------
// Static device scratch
// ------------------------------------------------------------------
__device__ __align__(16) __half g_UThi[TLEN][K1PAD];      // A1 [t][k]
__device__ __align__(16) __half g_UTlo[TLEN][K1PAD];
__device__ __align__(16) __half g_B1[2][K1PAD][NPH];      // B1 [k][n] single fp16
__device__ __align__(16) __half g_B2[2][K2PAD][NPH];      // B2 [k][n] single fp16
__device__ __align__(16) __half g_m1[2][TLEN][K2PAD];     // A2 [t][k] single fp16
__device__ __align__(16) __half g_PU[2][TLEN][NPH];       // fp16, 52 MB
__device__ __align__(16) float g_m2[2][TLEN][HD];
__device__ __align__(16) float g_b2T[2][NPH];
__device__ __align__(16) float g_prT[2][NPH];
__device__ float g_g[4 * HD];
__device__ float g_hB[2][HD];
__device__ float g_cB[2][HD];
__device__ float g_r[2][HD];
__device__ unsigned long long g_slot[2][2];

// ------------------------------------------------------------------
// helpers
// ------------------------------------------------------------------
__device__ __forceinline__ uint32_t smem_u32(const void* p) {
    uint32_t a;
    asm("{ .reg .u64 t; cvta.to.shared.u64 t, %1; cvt.u32.u64 %0, t; }" : "=r"(a) : "l"(p));
    return a;
}
__device__ __forceinline__ void cp16(uint32_t dst, const void* src) {
    asm volatile("cp.async.cg.shared.global [%0], [%1], 16;" :: "r"(dst), "l"(src));
}
#define CP_COMMIT() asm volatile("cp.async.commit_group;" ::: "memory")
#define CP_WAIT0()  asm volatile("cp.async.wait_group 0;" ::: "memory")

__device__ __forceinline__ void ldsm4(uint32_t* r, uint32_t addr) {
    asm volatile("ldmatrix.sync.aligned.m8n8.x4.shared.b16 {%0,%1,%2,%3}, [%4];"
                 : "=r"(r[0]), "=r"(r[1]), "=r"(r[2]), "=r"(r[3]) : "r"(addr));
}
__device__ __forceinline__ void ldsm4t(uint32_t* r, uint32_t addr) {
    asm volatile("ldmatrix.sync.aligned.m8n8.x4.trans.shared.b16 {%0,%1,%2,%3}, [%4];"
                 : "=r"(r[0]), "=r"(r[1]), "=r"(r[2]), "=r"(r[3]) : "r"(addr));
}
__device__ __forceinline__ void mma_f16(float* c, const uint32_t* a, const uint32_t* b) {
    asm volatile(
        "mma.sync.aligned.m16n8k16.row.col.f32.f16.f16.f32 "
        "{%0,%1,%2,%3}, {%4,%5,%6,%7}, {%8,%9}, {%0,%1,%2,%3};"
        : "+f"(c[0]), "+f"(c[1]), "+f"(c[2]), "+f"(c[3])
        : "r"(a[0]), "r"(a[1]), "r"(a[2]), "r"(a[3]), "r"(b[0]), "r"(b[1]));
}
__device__ __forceinline__ float sigm(float x) { return 1.0f / (1.0f + expf(-x)); }
__device__ __forceinline__ void split_f16(float v, __half& hi, __half& lo) {
    hi = __float2half(v);
    lo = __float2half(v - __half2float(hi));
}
__device__ __forceinline__ unsigned long long enc_max(float v, int t) {
    uint32_t u = __float_as_uint(v);
    u = (u & 0x80000000u) ? ~u : (u | 0x80000000u);
    return ((unsigned long long)u << 32) | (uint32_t)(TLEN - 1 - t);
}
__device__ __forceinline__ int dec_idx(unsigned long long s) {
    return TLEN - 1 - (int)(uint32_t)(s & 0xFFFFFFFFull);
}

// ------------------------------------------------------------------
// prep
// ------------------------------------------------------------------
__global__ void prep_kernel(const float* __restrict__ W1a, const float* __restrict__ W1b,
                            const float* __restrict__ W2a, const float* __restrict__ W2b,
                            const float* __restrict__ b2a, const float* __restrict__ b2b,
                            const float* __restrict__ h0,  const float* __restrict__ c0,
                            const float* __restrict__ U) {
    int idx0 = blockIdx.x * blockDim.x + threadIdx.x;
    int stride = gridDim.x * blockDim.x;
    for (int i = idx0; i < TLEN * K1PAD; i += stride) {
        int t = i / K1PAD, k = i - t * K1PAD;
        float v = (k < 2 * HD) ? U[(size_t)k * TLEN + t] : 0.f;
        __half hi, lo; split_f16(v, hi, lo);
        g_UThi[t][k] = hi; g_UTlo[t][k] = lo;
    }
    for (int i = idx0; i < 2 * K1PAD * NPH; i += stride) {
        int net = i / (K1PAD * NPH);
        int rem = i - net * (K1PAD * NPH);
        int k = rem / NPH, n = rem - k * NPH;
        int h = n >> 4, p = n & 15;
        const float* W1 = net ? W1b : W1a;
        float v = (k < 2 * HD) ? W1[(size_t)(p * HD + h) * 600 + k] : 0.f;
        g_B1[net][k][n] = __float2half(v);
    }
    for (int i = idx0; i < 2 * K2PAD * NPH; i += stride) {
        int net = i / (K2PAD * NPH);
        int rem = i - net * (K2PAD * NPH);
        int k = rem / NPH, n = rem - k * NPH;
        int h = n >> 4, p = n & 15;
        const float* W2 = net ? W2b : W2a;
        float v = (k < HD) ? W2[(size_t)(p * HD + h) * HD + k] : 0.f;
        g_B2[net][k][n] = __float2half(v);
    }
    for (int i = idx0; i < 2 * NPH; i += stride) {
        int net = i / NPH, n = i - net * NPH;
        int h = n >> 4, p = n & 15;
        const float* b2 = net ? b2b : b2a;
        g_b2T[net][n] = b2[p * HD + h];
    }
    // zero m1 K pad (k in [200,224))
    for (int i = idx0; i < 2 * TLEN * (K2PAD - HD); i += stride) {
        int net = i / (TLEN * (K2PAD - HD));
        int rem = i - net * (TLEN * (K2PAD - HD));
        int t = rem / (K2PAD - HD);
        int k = HD + (rem - t * (K2PAD - HD));
        g_m1[net][t][k] = __float2half(0.f);
    }
    if (idx0 < HD) { g_hB[1][idx0] = h0[idx0]; g_cB[1][idx0] = c0[idx0]; }
}

// ------------------------------------------------------------------
// mma.sync GEMM: C[t][n] = sum_k A[t][k]*B[k][n]; B = single fp16.
// MODE 0: A = UT hi/lo (2 MMAs, exact A), K=416 -> fp16 store to g_PU
// MODE 1: A = m1 single (1 MMA), K=224 -> +b2T, max over p -> g_m2[t][h]
// Block tile 128(m) x 128(n), 256 threads, 8 warps (4m x 2n), warp 32x64,
// K-chunk 32, 2-stage cp.async pipeline.
// ------------------------------------------------------------------
#define A_ROW_B   80
#define A_STG_B   10240
#define B_ROW_B   272
#define B_STG_B   8704
// MODE0: [Ahi 2stg | Alo 2stg | B 2stg];  MODE1: [A 2stg | B 2stg]
#define OFF_ALO    20480
#define OFF_B0     40960
#define OFF_B1     20480
#define GEMM_SMEM0 58368
#define GEMM_SMEM1 37888

template <int MODE>
__global__ void __launch_bounds__(256) gemm_mma() {
    extern __shared__ char smem[];
    const int tid    = threadIdx.x;
    const int lane   = tid & 31;
    const int wid    = tid >> 5;
    const int warp_m = wid & 3;
    const int warp_n = wid >> 2;
    const int net    = blockIdx.z;
    const int m0     = blockIdx.x * 128;
    const int n0     = blockIdx.y * 128;
    const int KPAD   = (MODE == 0) ? K1PAD : K2PAD;
    const int NC     = KPAD / 32;
    const int OFF_B  = (MODE == 0) ? OFF_B0 : OFF_B1;

    const __half* __restrict__ Ahi = (MODE == 0) ? &g_UThi[0][0] : &g_m1[net][0][0];
    const __half* __restrict__ Bp  = (MODE == 0) ? &g_B1[net][0][0] : &g_B2[net][0][0];

    const uint32_t sb = smem_u32(smem);

    const int arow = tid >> 1;
    const int aq   = (tid & 1) * 2;
    const int brow = tid >> 3;
    const int bq   = tid & 7;

    auto load_stage = [&](int stage, int kc) {
        const uint32_t as = sb + stage * A_STG_B + arow * A_ROW_B + aq * 16;
        const __half* ah = Ahi + (size_t)(m0 + arow) * KPAD + kc + aq * 8;
        cp16(as,      ah);
        cp16(as + 16, ah + 8);
        if (MODE == 0) {
            const __half* al = &g_UTlo[0][0] + (size_t)(m0 + arow) * K1PAD + kc + aq * 8;
            cp16(as + OFF_ALO,      al);
            cp16(as + OFF_ALO + 16, al + 8);
        }
        const uint32_t bs = sb + OFF_B + stage * B_STG_B + brow * B_ROW_B + bq * 32;
        const __half* bg = Bp + (size_t)(kc + brow) * NPH + n0 + bq * 16;
        cp16(bs,      bg);
        cp16(bs + 16, bg + 8);
    };

    float acc[2][8][4];
#pragma unroll
    for (int i = 0; i < 2; i++)
#pragma unroll
        for (int j = 0; j < 8; j++)
#pragma unroll
            for (int q = 0; q < 4; q++) acc[i][j][q] = 0.f;

    const int l15 = lane & 15;
    const int l16 = (lane >> 4) * 8;
    const uint32_t aBase = sb + (warp_m * 32 + l15) * A_ROW_B + l16 * 2;
    const uint32_t bBase = sb + OFF_B + l15 * B_ROW_B + (warp_n * 64 + l16) * 2;

    load_stage(0, 0);
    CP_COMMIT();

    for (int c = 0; c < NC; c++) {
        CP_WAIT0();
        __syncthreads();
        if (c + 1 < NC) { load_stage((c + 1) & 1, (c + 1) * 32); CP_COMMIT(); }
        const int stg = c & 1;
        const uint32_t aS = aBase + stg * A_STG_B;
        const uint32_t bS = bBase + stg * B_STG_B;
#pragma unroll
        for (int s = 0; s < 2; s++) {
            uint32_t ah[2][4], al[2][4];
#pragma unroll
            for (int i = 0; i < 2; i++) {
                uint32_t ao = aS + i * 16 * A_ROW_B + s * 32;
                ldsm4(ah[i], ao);
                if (MODE == 0) ldsm4(al[i], ao + OFF_ALO);
            }
#pragma unroll
            for (int half = 0; half < 2; half++) {
                uint32_t bb[4][2];
#pragma unroll
                for (int pr = 0; pr < 2; pr++) {
                    uint32_t r[4];
                    ldsm4t(r, bS + s * 16 * B_ROW_B + (half * 2 + pr) * 32);
                    bb[pr * 2][0] = r[0]; bb[pr * 2][1] = r[1];
                    bb[pr * 2 + 1][0] = r[2]; bb[pr * 2 + 1][1] = r[3];
                }
#pragma unroll
                for (int i = 0; i < 2; i++)
#pragma unroll
                    for (int j = 0; j < 4; j++) {
                        mma_f16(acc[i][half * 4 + j], ah[i], bb[j]);
                        if (MODE == 0) mma_f16(acc[i][half * 4 + j], al[i], bb[j]);
                    }
            }
        }
        __syncthreads();
    }

    const int g4 = lane >> 2;
    const int t2 = (lane & 3) * 2;
    if (MODE == 0) {
        __half* C = &g_PU[net][0][0];
#pragma unroll
        for (int i = 0; i < 2; i++) {
            int r0 = m0 + warp_m * 32 + i * 16 + g4;
#pragma unroll
            for (int j = 0; j < 8; j++) {
                int col = n0 + warp_n * 64 + j * 8 + t2;
                *(__half2*)&C[(size_t)r0 * NPH + col] =
                    __floats2half2_rn(acc[i][j][0], acc[i][j][1]);
                *(__half2*)&C[(size_t)(r0 + 8) * NPH + col] =
                    __floats2half2_rn(acc[i][j][2], acc[i][j][3]);
            }
        }
    } else {
        float b2v[8][2];
#pragma unroll
        for (int j = 0; j < 8; j++) {
            int col = n0 + warp_n * 64 + j * 8 + t2;
            b2v[j][0] = __ldg(&g_b2T[net][col]);
            b2v[j][1] = __ldg(&g_b2T[net][col + 1]);
        }
        const int h0i = (n0 + warp_n * 64) >> 4;
#pragma unroll
        for (int i = 0; i < 2; i++) {
#pragma unroll
            for (int hh = 0; hh < 4; hh++) {
                float mlo = -3.4e38f, mhi = -3.4e38f;
#pragma unroll
                for (int jj = 0; jj < 2; jj++) {
                    int j = hh * 2 + jj;
                    mlo = fmaxf(mlo, fmaxf(acc[i][j][0] + b2v[j][0], acc[i][j][1] + b2v[j][1]));
                    mhi = fmaxf(mhi, fmaxf(acc[i][j][2] + b2v[j][0], acc[i][j][3] + b2v[j][1]));
                }
                mlo = fmaxf(mlo, __shfl_xor_sync(0xffffffffu, mlo, 1));
                mlo = fmaxf(mlo, __shfl_xor_sync(0xffffffffu, mlo, 2));
                mhi = fmaxf(mhi, __shfl_xor_sync(0xffffffffu, mhi, 1));
                mhi = fmaxf(mhi, __shfl_xor_sync(0xffffffffu, mhi, 2));
                if ((lane & 3) == 0) {
                    int row = m0 + warp_m * 32 + i * 16 + g4;
                    g_m2[net][row][h0i + hh]     = mlo;
                    g_m2[net][row + 8][h0i + hh] = mhi;
                }
            }
        }
    }
}

// ------------------------------------------------------------------
// LSTM gates: 8 rows/block, 1 warp per row
// ------------------------------------------------------------------
__global__ void lstm_gates(const float* __restrict__ U, const float* __restrict__ W_ih,
                           const float* __restrict__ W_hh, const float* __restrict__ b_ih,
                           const float* __restrict__ b_hh, int it) {
    __shared__ float xs[800];
    __shared__ float hs[HD];
    int tid = threadIdx.x;
    int s = (it == 0) ? 0 : dec_idx(g_slot[(it + 1) & 1][0]);
    int e = (it == 0) ? 0 : dec_idx(g_slot[(it + 1) & 1][1]);
    if (blockIdx.x == 0 && tid == 0) {
        g_slot[it & 1][0] = 0ull;
        g_slot[it & 1][1] = 0ull;
    }
    for (int j = tid; j < 800; j += 256)
        xs[j] = (j < 400) ? U[(size_t)j * TLEN + s] : U[(size_t)(j - 400) * TLEN + e];
    const float* hprev = g_hB[(it + 1) & 1];
    for (int j = tid; j < HD; j += 256) hs[j] = hprev[j];
    __syncthreads();
    int row = blockIdx.x * 8 + (tid >> 5);
    int lane = tid & 31;
    const float* wr = &W_ih[(size_t)row * 800];
    float acc = 0.f;
    for (int k = lane; k < 800; k += 32) acc += wr[k] * xs[k];
    const float* wh = &W_hh[(size_t)row * HD];
    for (int k = lane; k < HD; k += 32) acc += wh[k] * hs[k];
#pragma unroll
    for (int o = 16; o; o >>= 1) acc += __shfl_xor_sync(0xffffffffu, acc, o);
    if (lane == 0) g_g[row] = acc + b_ih[row] + b_hh[row];
}

// ------------------------------------------------------------------
// fused LSTM update + r = tanh(WD @ [h_new, u_s, u_e]); 8 rows/block
// ------------------------------------------------------------------
__global__ void r_kernel(const float* __restrict__ U, const float* __restrict__ WDa,
                         const float* __restrict__ WDb, int it) {
    __shared__ float vs[1000];
    int tid = threadIdx.x;
    int s = (it == 0) ? 0 : dec_idx(g_slot[(it + 1) & 1][0]);
    int e = (it == 0) ? 0 : dec_idx(g_slot[(it + 1) & 1][1]);
    if (tid < HD) {
        float gi = g_g[tid], gf = g_g[HD + tid], gg = g_g[2 * HD + tid], go = g_g[3 * HD + tid];
        float c = sigm(gf) * g_cB[(it + 1) & 1][tid] + sigm(gi) * tanhf(gg);
        float h = sigm(go) * tanhf(c);
        vs[tid] = h;
        if (blockIdx.x == 0) { g_cB[it & 1][tid] = c; g_hB[it & 1][tid] = h; }
    }
    for (int j = tid; j < 800; j += 256) {
        int jj = HD + j;
        vs[jj] = (j < 400) ? U[(size_t)j * TLEN + s] : U[(size_t)(j - 400) * TLEN + e];
    }
    __syncthreads();
    int row = blockIdx.x * 8 + (tid >> 5);
    int lane = tid & 31;
    int net = row / HD;
    int rr = row - net * HD;
    const float* WD = net ? WDb : WDa;
    const float* wr = &WD[(size_t)rr * 1000];
    float acc = 0.f;
    for (int k = lane; k < 1000; k += 32) acc += wr[k] * vs[k];
#pragma unroll
    for (int o = 16; o; o >>= 1) acc += __shfl_xor_sync(0xffffffffu, acc, o);
    if (lane == 0) g_r[net][rr] = tanhf(acc);
}

// ------------------------------------------------------------------
// prT[net][h*16+p] = W1r[p][h]@r + b1[p][h]
// ------------------------------------------------------------------
__global__ void pr_kernel(const float* __restrict__ W1a, const float* __restrict__ W1b,
                          const float* __restrict__ b1a, const float* __restrict__ b1b) {
    int o = blockIdx.x * 8 + (threadIdx.x >> 5);
    int lane = threadIdx.x & 31;
    int net = o / NPH;
    int n = o - net * NPH;
    int h = n >> 4, p = n & 15;
    const float* W1 = net ? W1b : W1a;
    const float* b1 = net ? b1b : b1a;
    const float* w = &W1[(size_t)(p * HD + h) * 600 + 400];
    const float* r = g_r[net];
    float acc = 0.f;
    for (int k = lane; k < HD; k += 32) acc += w[k] * r[k];
#pragma unroll
    for (int o2 = 16; o2; o2 >>= 1) acc += __shfl_xor_sync(0xffffffffu, acc, o2);
    if (lane == 0) g_prT[net][n] = acc + b1[p * HD + h];
}

// ------------------------------------------------------------------
// m1[t][h] = max_p(PU[t][h*16+p] + prT[h*16+p]) -> single fp16
// ------------------------------------------------------------------
__global__ void m1_kernel() {
    int t = blockIdx.x, net = blockIdx.y;
    int h = threadIdx.x;
    if (h >= HD) return;
    const __half2* pu = (const __half2*)&g_PU[net][t][h << 4];
    const float4* pr = (const float4*)&g_prT[net][h << 4];
    float m = -3.4e38f;
#pragma unroll
    for (int q = 0; q < 4; q++) {
        float4 b = pr[q];
        float2 a0 = __half22float2(pu[q * 2]);
        float2 a1 = __half22float2(pu[q * 2 + 1]);
        m = fmaxf(m, fmaxf(fmaxf(a0.x + b.x, a0.y + b.y), fmaxf(a1.x + b.z, a1.y + b.w)));
    }
    g_m1[net][t][h] = __float2half(m);
}

// ------------------------------------------------------------------
// scores + fused argmax: 32 t per block, 512 threads (round-5 proven shape)
// ------------------------------------------------------------------
#define SCORE_SMEM ((32 * 408 + 16 * 401 + 64) * 4)
__global__ void __launch_bounds__(512) score_kernel(
        const float* __restrict__ W3a, const float* __restrict__ W3b,
        const float* __restrict__ b3a, const float* __restrict__ b3b,
        float* __restrict__ out, int it, int maxI) {
    extern __shared__ float sm[];
    float* ms  = sm;                 // [32][408]
    float* w3s = sm + 32 * 408;      // [16][401]
    float* bmx = w3s + 16 * 401;     // [32]
    int*   bmi = (int*)(bmx + 32);   // [32]
    int net = blockIdx.y;
    int t0 = blockIdx.x * 32;
    int tid = threadIdx.x;
    const float* W3 = net ? W3b : W3a;
    for (int idx = tid; idx < 6400; idx += 512) {
        int p = idx / 400, d = idx - p * 400;
        w3s[p * 401 + d] = W3[p * 400 + d];
    }
    for (int idx = tid; idx < 32 * HD; idx += 512) {
        int tt = idx / HD, h = idx - tt * HD;
        int t = t0 + tt;
        ms[tt * 408 + h] = __half2float(g_m1[net][t][h]);
        ms[tt * 408 + 200 + h] = g_m2[net][t][h];
    }
    __syncthreads();
    int tt = tid >> 4, p = tid & 15;
    float acc = (net ? b3b : b3a)[p];
    const float* msr = &ms[tt * 408];
    const float* w3r = &w3s[p * 401];
#pragma unroll 4
    for (int d = 0; d < 400; d++) acc = fmaf(msr[d], w3r[d], acc);
#pragma unroll
    for (int o = 8; o; o >>= 1) acc = fmaxf(acc, __shfl_xor_sync(0xffffffffu, acc, o));
    if (p == 0) {
        out[((size_t)net * maxI + it) * TLEN + t0 + tt] = acc;
        bmx[tt] = acc;
        bmi[tt] = t0 + tt;
    }
    __syncthreads();
    if (tid == 0) {
        float bv = bmx[0]; int bi = bmi[0];
        for (int q = 1; q < 32; q++) {
            if (bmx[q] > bv) { bv = bmx[q]; bi = bmi[q]; }
        }
        atomicMax(&g_slot[it & 1][net], enc_max(bv, bi));
    }
}

__global__ void finalize_kernel(float* __restrict__ out, int maxI) {
    out[(size_t)2 * maxI * TLEN + 0] = (float)dec_idx(g_slot[(maxI - 1) & 1][0]);
    out[(size_t)2 * maxI * TLEN + 1] = (float)dec_idx(g_slot[(maxI - 1) & 1][1]);
}

// ------------------------------------------------------------------
// launch
// ------------------------------------------------------------------
extern "C" void kernel_launch(void* const* d_in, const int* in_sizes, int n_in,
                              void* d_out, int out_size) {
    const float* U    = (const float*)d_in[0];
    const float* h0   = (const float*)d_in[2];
    const float* c0   = (const float*)d_in[3];
    const float* W_ih = (const float*)d_in[4];
    const float* W_hh = (const float*)d_in[5];
    const float* b_ih = (const float*)d_in[6];
    const float* b_hh = (const float*)d_in[7];
    const float* WD_a = (const float*)d_in[8];
    const float* W1_a = (const float*)d_in[9];
    const float* b1_a = (const float*)d_in[10];
    const float* W2_a = (const float*)d_in[11];
    const float* b2_a = (const float*)d_in[12];
    const float* W3_a = (const float*)d_in[13];
    const float* b3_a = (const float*)d_in[14];
    const float* WD_b = (const float*)d_in[15];
    const float* W1_b = (const float*)d_in[16];
    const float* b1_b = (const float*)d_in[17];
    const float* W2_b = (const float*)d_in[18];
    const float* b2_b = (const float*)d_in[19];
    const float* W3_b = (const float*)d_in[20];
    const float* b3_b = (const float*)d_in[21];
    float* out = (float*)d_out;

    int maxI = out_size / (2 * TLEN);
    if (maxI < 1) maxI = 1;
    int write_se = (out_size >= 2 * maxI * TLEN + 2) ? 1 : 0;

    cudaFuncSetAttribute(gemm_mma<0>, cudaFuncAttributeMaxDynamicSharedMemorySize, GEMM_SMEM0);
    cudaFuncSetAttribute(gemm_mma<1>, cudaFuncAttributeMaxDynamicSharedMemorySize, GEMM_SMEM1);
    cudaFuncSetAttribute(score_kernel, cudaFuncAttributeMaxDynamicSharedMemorySize, SCORE_SMEM);

    prep_kernel<<<2048, 256>>>(W1_a, W1_b, W2_a, W2_b, b2_a, b2_b, h0, c0, U);
    gemm_mma<0><<<dim3(TLEN / 128, NPH / 128, 2), 256, GEMM_SMEM0>>>();

    for (int it = 0; it < maxI; it++) {
        lstm_gates<<<100, 256>>>(U, W_ih, W_hh, b_ih, b_hh, it);
        r_kernel<<<50, 256>>>(U, WD_a, WD_b, it);
        pr_kernel<<<800, 256>>>(W1_a, W1_b, b1_a, b1_b);
        m1_kernel<<<dim3(TLEN, 2), 256>>>();
        gemm_mma<1><<<dim3(TLEN / 128, NPH / 128, 2), 256, GEMM_SMEM1>>>();
        score_kernel<<<dim3(TLEN / 32, 2), 512, SCORE_SMEM>>>(W3_a, W3_b, b3_a, b3_b, out, it, maxI);
    }
    if (write_se) finalize_kernel<<<1, 1>>>(out, maxI);
}

// round 9
// speedup vs baseline: 4.9627x; 1.1129x over previous
#include <cuda_runtime.h>
#include <cuda_fp16.h>
#include <math.h>
#include <stdint.h>

#define HD    200
#define POOL  16
#define TLEN  4096
#define NPH   3200   // POOL*HD
#define K1PAD 416    // pad of 2*HD=400 to mult of 32
#define K2PAD 224    // pad of HD=200 to mult of 32

// ------------------------------------------------------------------
// Static device scratch
// ------------------------------------------------------------------
__device__ __align__(16) __half g_UT[TLEN][K1PAD];        // A1 [t][k] single fp16
__device__ __align__(16) __half g_B1[2][K1PAD][NPH];      // B1 [k][n] single fp16
__device__ __align__(16) __half g_B2[2][K2PAD][NPH];      // B2 [k][n] single fp16
__device__ __align__(16) __half g_m1[2][TLEN][K2PAD];     // A2 [t][k] single fp16
__device__ __align__(16) __half g_PU[2][TLEN][NPH];       // fp16, 52 MB
__device__ __align__(16) float g_m2[2][TLEN][HD];
__device__ __align__(16) float g_b2T[2][NPH];
__device__ __align__(16) float g_prT[2][NPH];
__device__ float g_g[4 * HD];
__device__ float g_hB[2][HD];
__device__ float g_cB[2][HD];
__device__ float g_r[2][HD];
__device__ unsigned long long g_slot[2][2];

// ------------------------------------------------------------------
// helpers
// ------------------------------------------------------------------
__device__ __forceinline__ uint32_t smem_u32(const void* p) {
    uint32_t a;
    asm("{ .reg .u64 t; cvta.to.shared.u64 t, %1; cvt.u32.u64 %0, t; }" : "=r"(a) : "l"(p));
    return a;
}
__device__ __forceinline__ void cp16(uint32_t dst, const void* src) {
    asm volatile("cp.async.cg.shared.global [%0], [%1], 16;" :: "r"(dst), "l"(src));
}
#define CP_COMMIT() asm volatile("cp.async.commit_group;" ::: "memory")
#define CP_WAIT0()  asm volatile("cp.async.wait_group 0;" ::: "memory")

__device__ __forceinline__ void ldsm4(uint32_t* r, uint32_t addr) {
    asm volatile("ldmatrix.sync.aligned.m8n8.x4.shared.b16 {%0,%1,%2,%3}, [%4];"
                 : "=r"(r[0]), "=r"(r[1]), "=r"(r[2]), "=r"(r[3]) : "r"(addr));
}
__device__ __forceinline__ void ldsm4t(uint32_t* r, uint32_t addr) {
    asm volatile("ldmatrix.sync.aligned.m8n8.x4.trans.shared.b16 {%0,%1,%2,%3}, [%4];"
                 : "=r"(r[0]), "=r"(r[1]), "=r"(r[2]), "=r"(r[3]) : "r"(addr));
}
__device__ __forceinline__ void mma_f16(float* c, const uint32_t* a, const uint32_t* b) {
    asm volatile(
        "mma.sync.aligned.m16n8k16.row.col.f32.f16.f16.f32 "
        "{%0,%1,%2,%3}, {%4,%5,%6,%7}, {%8,%9}, {%0,%1,%2,%3};"
        : "+f"(c[0]), "+f"(c[1]), "+f"(c[2]), "+f"(c[3])
        : "r"(a[0]), "r"(a[1]), "r"(a[2]), "r"(a[3]), "r"(b[0]), "r"(b[1]));
}
__device__ __forceinline__ float sigm(float x) { return 1.0f / (1.0f + expf(-x)); }
__device__ __forceinline__ unsigned long long enc_max(float v, int t) {
    uint32_t u = __float_as_uint(v);
    u = (u & 0x80000000u) ? ~u : (u | 0x80000000u);
    return ((unsigned long long)u << 32) | (uint32_t)(TLEN - 1 - t);
}
__device__ __forceinline__ int dec_idx(unsigned long long s) {
    return TLEN - 1 - (int)(uint32_t)(s & 0xFFFFFFFFull);
}
__device__ __forceinline__ float dot4(float4 a, float4 b) {
    return a.x * b.x + a.y * b.y + a.z * b.z + a.w * b.w;
}

// ------------------------------------------------------------------
// prep
// ------------------------------------------------------------------
__global__ void prep_kernel(const float* __restrict__ W1a, const float* __restrict__ W1b,
                            const float* __restrict__ W2a, const float* __restrict__ W2b,
                            const float* __restrict__ b2a, const float* __restrict__ b2b,
                            const float* __restrict__ h0,  const float* __restrict__ c0,
                            const float* __restrict__ U) {
    int idx0 = blockIdx.x * blockDim.x + threadIdx.x;
    int stride = gridDim.x * blockDim.x;
    for (int i = idx0; i < TLEN * K1PAD; i += stride) {
        int t = i / K1PAD, k = i - t * K1PAD;
        float v = (k < 2 * HD) ? U[(size_t)k * TLEN + t] : 0.f;
        g_UT[t][k] = __float2half(v);
    }
    for (int i = idx0; i < 2 * K1PAD * NPH; i += stride) {
        int net = i / (K1PAD * NPH);
        int rem = i - net * (K1PAD * NPH);
        int k = rem / NPH, n = rem - k * NPH;
        int h = n >> 4, p = n & 15;
        const float* W1 = net ? W1b : W1a;
        float v = (k < 2 * HD) ? W1[(size_t)(p * HD + h) * 600 + k] : 0.f;
        g_B1[net][k][n] = __float2half(v);
    }
    for (int i = idx0; i < 2 * K2PAD * NPH; i += stride) {
        int net = i / (K2PAD * NPH);
        int rem = i - net * (K2PAD * NPH);
        int k = rem / NPH, n = rem - k * NPH;
        int h = n >> 4, p = n & 15;
        const float* W2 = net ? W2b : W2a;
        float v = (k < HD) ? W2[(size_t)(p * HD + h) * HD + k] : 0.f;
        g_B2[net][k][n] = __float2half(v);
    }
    for (int i = idx0; i < 2 * NPH; i += stride) {
        int net = i / NPH, n = i - net * NPH;
        int h = n >> 4, p = n & 15;
        const float* b2 = net ? b2b : b2a;
        g_b2T[net][n] = b2[p * HD + h];
    }
    // zero m1 K pad (k in [200,224))
    for (int i = idx0; i < 2 * TLEN * (K2PAD - HD); i += stride) {
        int net = i / (TLEN * (K2PAD - HD));
        int rem = i - net * (TLEN * (K2PAD - HD));
        int t = rem / (K2PAD - HD);
        int k = HD + (rem - t * (K2PAD - HD));
        g_m1[net][t][k] = __float2half(0.f);
    }
    if (idx0 < HD) { g_hB[1][idx0] = h0[idx0]; g_cB[1][idx0] = c0[idx0]; }
}

// ------------------------------------------------------------------
// mma.sync GEMM: C[t][n] = sum_k A[t][k]*B[k][n]; A,B single fp16, 1 MMA.
// MODE 0: A=UT (K=416), B=B1 -> fp16 store to g_PU
// MODE 1: A=m1 (K=224), B=B2 -> +b2T, max over p -> g_m2[t][h]
// Block tile 128(m) x 128(n), 256 threads, 8 warps (4m x 2n), warp 32x64,
// K-chunk 32, 2-stage cp.async pipeline.
// ------------------------------------------------------------------
#define A_ROW_B   80
#define A_STG_B   10240
#define B_ROW_B   272
#define B_STG_B   8704
#define OFF_B     20480
#define GEMM_SMEM 37888

template <int MODE>
__global__ void __launch_bounds__(256) gemm_mma() {
    extern __shared__ char smem[];
    const int tid    = threadIdx.x;
    const int lane   = tid & 31;
    const int wid    = tid >> 5;
    const int warp_m = wid & 3;
    const int warp_n = wid >> 2;
    const int net    = blockIdx.z;
    const int m0     = blockIdx.x * 128;
    const int n0     = blockIdx.y * 128;
    const int KPAD   = (MODE == 0) ? K1PAD : K2PAD;
    const int NC     = KPAD / 32;

    const __half* __restrict__ Ap = (MODE == 0) ? &g_UT[0][0] : &g_m1[net][0][0];
    const __half* __restrict__ Bp = (MODE == 0) ? &g_B1[net][0][0] : &g_B2[net][0][0];

    const uint32_t sb = smem_u32(smem);

    const int arow = tid >> 1;
    const int aq   = (tid & 1) * 2;
    const int brow = tid >> 3;
    const int bq   = tid & 7;

    auto load_stage = [&](int stage, int kc) {
        const uint32_t as = sb + stage * A_STG_B + arow * A_ROW_B + aq * 16;
        const __half* ah = Ap + (size_t)(m0 + arow) * KPAD + kc + aq * 8;
        cp16(as,      ah);
        cp16(as + 16, ah + 8);
        const uint32_t bs = sb + OFF_B + stage * B_STG_B + brow * B_ROW_B + bq * 32;
        const __half* bg = Bp + (size_t)(kc + brow) * NPH + n0 + bq * 16;
        cp16(bs,      bg);
        cp16(bs + 16, bg + 8);
    };

    float acc[2][8][4];
#pragma unroll
    for (int i = 0; i < 2; i++)
#pragma unroll
        for (int j = 0; j < 8; j++)
#pragma unroll
            for (int q = 0; q < 4; q++) acc[i][j][q] = 0.f;

    const int l15 = lane & 15;
    const int l16 = (lane >> 4) * 8;
    const uint32_t aBase = sb + (warp_m * 32 + l15) * A_ROW_B + l16 * 2;
    const uint32_t bBase = sb + OFF_B + l15 * B_ROW_B + (warp_n * 64 + l16) * 2;

    load_stage(0, 0);
    CP_COMMIT();

    for (int c = 0; c < NC; c++) {
        CP_WAIT0();
        __syncthreads();
        if (c + 1 < NC) { load_stage((c + 1) & 1, (c + 1) * 32); CP_COMMIT(); }
        const int stg = c & 1;
        const uint32_t aS = aBase + stg * A_STG_B;
        const uint32_t bS = bBase + stg * B_STG_B;
#pragma unroll
        for (int s = 0; s < 2; s++) {
            uint32_t ah[2][4];
#pragma unroll
            for (int i = 0; i < 2; i++)
                ldsm4(ah[i], aS + i * 16 * A_ROW_B + s * 32);
#pragma unroll
            for (int half = 0; half < 2; half++) {
                uint32_t bb[4][2];
#pragma unroll
                for (int pr = 0; pr < 2; pr++) {
                    uint32_t r[4];
                    ldsm4t(r, bS + s * 16 * B_ROW_B + (half * 2 + pr) * 32);
                    bb[pr * 2][0] = r[0]; bb[pr * 2][1] = r[1];
                    bb[pr * 2 + 1][0] = r[2]; bb[pr * 2 + 1][1] = r[3];
                }
#pragma unroll
                for (int i = 0; i < 2; i++)
#pragma unroll
                    for (int j = 0; j < 4; j++)
                        mma_f16(acc[i][half * 4 + j], ah[i], bb[j]);
            }
        }
        __syncthreads();
    }

    const int g4 = lane >> 2;
    const int t2 = (lane & 3) * 2;
    if (MODE == 0) {
        __half* C = &g_PU[net][0][0];
#pragma unroll
        for (int i = 0; i < 2; i++) {
            int r0 = m0 + warp_m * 32 + i * 16 + g4;
#pragma unroll
            for (int j = 0; j < 8; j++) {
                int col = n0 + warp_n * 64 + j * 8 + t2;
                *(__half2*)&C[(size_t)r0 * NPH + col] =
                    __floats2half2_rn(acc[i][j][0], acc[i][j][1]);
                *(__half2*)&C[(size_t)(r0 + 8) * NPH + col] =
                    __floats2half2_rn(acc[i][j][2], acc[i][j][3]);
            }
        }
    } else {
        float b2v[8][2];
#pragma unroll
        for (int j = 0; j < 8; j++) {
            int col = n0 + warp_n * 64 + j * 8 + t2;
            b2v[j][0] = __ldg(&g_b2T[net][col]);
            b2v[j][1] = __ldg(&g_b2T[net][col + 1]);
        }
        const int h0i = (n0 + warp_n * 64) >> 4;
#pragma unroll
        for (int i = 0; i < 2; i++) {
#pragma unroll
            for (int hh = 0; hh < 4; hh++) {
                float mlo = -3.4e38f, mhi = -3.4e38f;
#pragma unroll
                for (int jj = 0; jj < 2; jj++) {
                    int j = hh * 2 + jj;
                    mlo = fmaxf(mlo, fmaxf(acc[i][j][0] + b2v[j][0], acc[i][j][1] + b2v[j][1]));
                    mhi = fmaxf(mhi, fmaxf(acc[i][j][2] + b2v[j][0], acc[i][j][3] + b2v[j][1]));
                }
                mlo = fmaxf(mlo, __shfl_xor_sync(0xffffffffu, mlo, 1));
                mlo = fmaxf(mlo, __shfl_xor_sync(0xffffffffu, mlo, 2));
                mhi = fmaxf(mhi, __shfl_xor_sync(0xffffffffu, mhi, 1));
                mhi = fmaxf(mhi, __shfl_xor_sync(0xffffffffu, mhi, 2));
                if ((lane & 3) == 0) {
                    int row = m0 + warp_m * 32 + i * 16 + g4;
                    g_m2[net][row][h0i + hh]     = mlo;
                    g_m2[net][row + 8][h0i + hh] = mhi;
                }
            }
        }
    }
}

// ------------------------------------------------------------------
// LSTM gates: 8 rows/block, 1 warp per row, float4 dots
// ------------------------------------------------------------------
__global__ void lstm_gates(const float* __restrict__ U, const float* __restrict__ W_ih,
                           const float* __restrict__ W_hh, const float* __restrict__ b_ih,
                           const float* __restrict__ b_hh, int it) {
    __shared__ __align__(16) float xs[800];
    __shared__ __align__(16) float hs[HD];
    int tid = threadIdx.x;
    int s = (it == 0) ? 0 : dec_idx(g_slot[(it + 1) & 1][0]);
    int e = (it == 0) ? 0 : dec_idx(g_slot[(it + 1) & 1][1]);
    if (blockIdx.x == 0 && tid == 0) {
        g_slot[it & 1][0] = 0ull;
        g_slot[it & 1][1] = 0ull;
    }
    for (int j = tid; j < 800; j += 256)
        xs[j] = (j < 400) ? U[(size_t)j * TLEN + s] : U[(size_t)(j - 400) * TLEN + e];
    const float* hprev = g_hB[(it + 1) & 1];
    for (int j = tid; j < HD; j += 256) hs[j] = hprev[j];
    __syncthreads();
    int row = blockIdx.x * 8 + (tid >> 5);
    int lane = tid & 31;
    const float4* w4  = (const float4*)&W_ih[(size_t)row * 800];   // 200 float4
    const float4* xs4 = (const float4*)xs;
    float acc = 0.f;
    for (int k = lane; k < 200; k += 32) acc += dot4(w4[k], xs4[k]);
    const float4* wh4 = (const float4*)&W_hh[(size_t)row * HD];    // 50 float4
    const float4* hs4 = (const float4*)hs;
    if (lane < 25) {
        acc += dot4(wh4[lane], hs4[lane]);
        acc += dot4(wh4[lane + 25], hs4[lane + 25]);
    }
#pragma unroll
    for (int o = 16; o; o >>= 1) acc += __shfl_xor_sync(0xffffffffu, acc, o);
    if (lane == 0) g_g[row] = acc + b_ih[row] + b_hh[row];
}

// ------------------------------------------------------------------
// fused LSTM update + r = tanh(WD @ [h_new, u_s, u_e]); float4 dots
// ------------------------------------------------------------------
__global__ void r_kernel(const float* __restrict__ U, const float* __restrict__ WDa,
                         const float* __restrict__ WDb, int it) {
    __shared__ __align__(16) float vs[1000];
    int tid = threadIdx.x;
    int s = (it == 0) ? 0 : dec_idx(g_slot[(it + 1) & 1][0]);
    int e = (it == 0) ? 0 : dec_idx(g_slot[(it + 1) & 1][1]);
    if (tid < HD) {
        float gi = g_g[tid], gf = g_g[HD + tid], gg = g_g[2 * HD + tid], go = g_g[3 * HD + tid];
        float c = sigm(gf) * g_cB[(it + 1) & 1][tid] + sigm(gi) * tanhf(gg);
        float h = sigm(go) * tanhf(c);
        vs[tid] = h;
        if (blockIdx.x == 0) { g_cB[it & 1][tid] = c; g_hB[it & 1][tid] = h; }
    }
    for (int j = tid; j < 800; j += 256) {
        int jj = HD + j;
        vs[jj] = (j < 400) ? U[(size_t)j * TLEN + s] : U[(size_t)(j - 400) * TLEN + e];
    }
    __syncthreads();
    int row = blockIdx.x * 8 + (tid >> 5);
    int lane = tid & 31;
    int net = row / HD;
    int rr = row - net * HD;
    const float* WD = net ? WDb : WDa;
    const float4* w4  = (const float4*)&WD[(size_t)rr * 1000];   // 250 float4
    const float4* vs4 = (const float4*)vs;
    float acc = 0.f;
    for (int k = lane; k < 250; k += 32) acc += dot4(w4[k], vs4[k]);
#pragma unroll
    for (int o = 16; o; o >>= 1) acc += __shfl_xor_sync(0xffffffffu, acc, o);
    if (lane == 0) g_r[net][rr] = tanhf(acc);
}

// ------------------------------------------------------------------
// prT[net][h*16+p] = W1r[p][h]@r + b1[p][h]; float4 dots
// ------------------------------------------------------------------
__global__ void pr_kernel(const float* __restrict__ W1a, const float* __restrict__ W1b,
                          const float* __restrict__ b1a, const float* __restrict__ b1b) {
    int o = blockIdx.x * 8 + (threadIdx.x >> 5);
    int lane = threadIdx.x & 31;
    int net = o / NPH;
    int n = o - net * NPH;
    int h = n >> 4, p = n & 15;
    const float* W1 = net ? W1b : W1a;
    const float* b1 = net ? b1b : b1a;
    const float4* w4 = (const float4*)&W1[(size_t)(p * HD + h) * 600 + 400];  // 50 float4
    const float4* r4 = (const float4*)g_r[net];
    float acc = 0.f;
    if (lane < 25) {
        acc += dot4(w4[lane], r4[lane]);
        acc += dot4(w4[lane + 25], r4[lane + 25]);
    }
#pragma unroll
    for (int o2 = 16; o2; o2 >>= 1) acc += __shfl_xor_sync(0xffffffffu, acc, o2);
    if (lane == 0) g_prT[net][n] = acc + b1[p * HD + h];
}

// ------------------------------------------------------------------
// m1[t][h] = max_p(PU[t][h*16+p] + prT[h*16+p]) -> single fp16
// grid (TLEN/16, 2), 256 threads, 16 t per block
// ------------------------------------------------------------------
__global__ void m1_kernel() {
    int net = blockIdx.y;
    int t0 = blockIdx.x * 16;
    int tid = threadIdx.x;
    for (int item = tid; item < 16 * HD; item += 256) {
        int tt = item / HD, h = item - tt * HD;
        int t = t0 + tt;
        const __half2* pu = (const __half2*)&g_PU[net][t][h << 4];
        const float4* pr = (const float4*)&g_prT[net][h << 4];
        float m = -3.4e38f;
#pragma unroll
        for (int q = 0; q < 4; q++) {
            float4 b = pr[q];
            float2 a0 = __half22float2(pu[q * 2]);
            float2 a1 = __half22float2(pu[q * 2 + 1]);
            m = fmaxf(m, fmaxf(fmaxf(a0.x + b.x, a0.y + b.y), fmaxf(a1.x + b.z, a1.y + b.w)));
        }
        g_m1[net][t][h] = __float2half(m);
    }
}

// ------------------------------------------------------------------
// scores + fused argmax: 32 t per block, 512 threads
// ------------------------------------------------------------------
#define SCORE_SMEM ((32 * 408 + 16 * 401 + 64) * 4)
__global__ void __launch_bounds__(512) score_kernel(
        const float* __restrict__ W3a, const float* __restrict__ W3b,
        const float* __restrict__ b3a, const float* __restrict__ b3b,
        float* __restrict__ out, int it, int maxI) {
    extern __shared__ float sm[];
    float* ms  = sm;                 // [32][408]
    float* w3s = sm + 32 * 408;      // [16][401]
    float* bmx = w3s + 16 * 401;     // [32]
    int*   bmi = (int*)(bmx + 32);   // [32]
    int net = blockIdx.y;
    int t0 = blockIdx.x * 32;
    int tid = threadIdx.x;
    const float* W3 = net ? W3b : W3a;
    for (int idx = tid; idx < 6400; idx += 512) {
        int p = idx / 400, d = idx - p * 400;
        w3s[p * 401 + d] = W3[p * 400 + d];
    }
    for (int idx = tid; idx < 32 * HD; idx += 512) {
        int tt = idx / HD, h = idx - tt * HD;
        int t = t0 + tt;
        ms[tt * 408 + h] = __half2float(g_m1[net][t][h]);
        ms[tt * 408 + 200 + h] = g_m2[net][t][h];
    }
    __syncthreads();
    int tt = tid >> 4, p = tid & 15;
    float acc = (net ? b3b : b3a)[p];
    const float* msr = &ms[tt * 408];
    const float* w3r = &w3s[p * 401];
#pragma unroll 4
    for (int d = 0; d < 400; d++) acc = fmaf(msr[d], w3r[d], acc);
#pragma unroll
    for (int o = 8; o; o >>= 1) acc = fmaxf(acc, __shfl_xor_sync(0xffffffffu, acc, o));
    if (p == 0) {
        out[((size_t)net * maxI + it) * TLEN + t0 + tt] = acc;
        bmx[tt] = acc;
        bmi[tt] = t0 + tt;
    }
    __syncthreads();
    if (tid == 0) {
        float bv = bmx[0]; int bi = bmi[0];
        for (int q = 1; q < 32; q++) {
            if (bmx[q] > bv) { bv = bmx[q]; bi = bmi[q]; }
        }
        atomicMax(&g_slot[it & 1][net], enc_max(bv, bi));
    }
}

__global__ void finalize_kernel(float* __restrict__ out, int maxI) {
    out[(size_t)2 * maxI * TLEN + 0] = (float)dec_idx(g_slot[(maxI - 1) & 1][0]);
    out[(size_t)2 * maxI * TLEN + 1] = (float)dec_idx(g_slot[(maxI - 1) & 1][1]);
}

// ------------------------------------------------------------------
// launch
// ------------------------------------------------------------------
extern "C" void kernel_launch(void* const* d_in, const int* in_sizes, int n_in,
                              void* d_out, int out_size) {
    const float* U    = (const float*)d_in[0];
    const float* h0   = (const float*)d_in[2];
    const float* c0   = (const float*)d_in[3];
    const float* W_ih = (const float*)d_in[4];
    const float* W_hh = (const float*)d_in[5];
    const float* b_ih = (const float*)d_in[6];
    const float* b_hh = (const float*)d_in[7];
    const float* WD_a = (const float*)d_in[8];
    const float* W1_a = (const float*)d_in[9];
    const float* b1_a = (const float*)d_in[10];
    const float* W2_a = (const float*)d_in[11];
    const float* b2_a = (const float*)d_in[12];
    const float* W3_a = (const float*)d_in[13];
    const float* b3_a = (const float*)d_in[14];
    const float* WD_b = (const float*)d_in[15];
    const float* W1_b = (const float*)d_in[16];
    const float* b1_b = (const float*)d_in[17];
    const float* W2_b = (const float*)d_in[18];
    const float* b2_b = (const float*)d_in[19];
    const float* W3_b = (const float*)d_in[20];
    const float* b3_b = (const float*)d_in[21];
    float* out = (float*)d_out;

    int maxI = out_size / (2 * TLEN);
    if (maxI < 1) maxI = 1;
    int write_se = (out_size >= 2 * maxI * TLEN + 2) ? 1 : 0;

    cudaFuncSetAttribute(gemm_mma<0>, cudaFuncAttributeMaxDynamicSharedMemorySize, GEMM_SMEM);
    cudaFuncSetAttribute(gemm_mma<1>, cudaFuncAttributeMaxDynamicSharedMemorySize, GEMM_SMEM);
    cudaFuncSetAttribute(score_kernel, cudaFuncAttributeMaxDynamicSharedMemorySize, SCORE_SMEM);

    prep_kernel<<<2048, 256>>>(W1_a, W1_b, W2_a, W2_b, b2_a, b2_b, h0, c0, U);
    gemm_mma<0><<<dim3(TLEN / 128, NPH / 128, 2), 256, GEMM_SMEM>>>();

    for (int it = 0; it < maxI; it++) {
        lstm_gates<<<100, 256>>>(U, W_ih, W_hh, b_ih, b_hh, it);
        r_kernel<<<50, 256>>>(U, WD_a, WD_b, it);
        pr_kernel<<<800, 256>>>(W1_a, W1_b, b1_a, b1_b);
        m1_kernel<<<dim3(TLEN / 16, 2), 256>>>();
        gemm_mma<1><<<dim3(TLEN / 128, NPH / 128, 2), 256, GEMM_SMEM>>>();
        score_kernel<<<dim3(TLEN / 32, 2), 512, SCORE_SMEM>>>(W3_a, W3_b, b3_a, b3_b, out, it, maxI);
    }
    if (write_se) finalize_kernel<<<1, 1>>>(out, maxI);
}

// round 10
// speedup vs baseline: 5.1128x; 1.0303x over previous
#include <cuda_runtime.h>
#include <cuda_fp16.h>
#include <math.h>
#include <stdint.h>

#define HD    200
#define POOL  16
#define TLEN  4096
#define NPH   3200   // POOL*HD
#define K1PAD 416    // pad of 2*HD=400 to mult of 32
#define K2PAD 224    // pad of HD=200 to mult of 32

// ------------------------------------------------------------------
// Static device scratch
// ------------------------------------------------------------------
__device__ __align__(16) __half g_UT[TLEN][K1PAD];        // A1 [t][k]
__device__ __align__(16) __half g_B1[2][K1PAD][NPH];      // B1 [k][n]
__device__ __align__(16) __half g_B2[2][K2PAD][NPH];      // B2 [k][n]
__device__ __align__(16) __half g_m1[2][TLEN][K2PAD];     // A2 [t][k]
__device__ __align__(16) __half g_PU[2][TLEN][NPH];       // fp16, 52 MB
__device__ __align__(16) float g_m2[2][TLEN][HD];
__device__ __align__(16) float g_b2T[2][NPH];
__device__ __align__(16) float g_prT[2][NPH];
__device__ float g_g[4 * HD];
__device__ float g_hB[2][HD];
__device__ float g_cB[2][HD];
__device__ float g_r[2][HD];
__device__ unsigned long long g_slot[2][2];

// ------------------------------------------------------------------
// helpers
// ------------------------------------------------------------------
__device__ __forceinline__ uint32_t smem_u32(const void* p) {
    uint32_t a;
    asm("{ .reg .u64 t; cvta.to.shared.u64 t, %1; cvt.u32.u64 %0, t; }" : "=r"(a) : "l"(p));
    return a;
}
__device__ __forceinline__ void cp16(uint32_t dst, const void* src) {
    asm volatile("cp.async.cg.shared.global [%0], [%1], 16;" :: "r"(dst), "l"(src));
}
#define CP_COMMIT() asm volatile("cp.async.commit_group;" ::: "memory")
#define CP_WAIT1()  asm volatile("cp.async.wait_group 1;" ::: "memory")

__device__ __forceinline__ void ldsm4(uint32_t* r, uint32_t addr) {
    asm volatile("ldmatrix.sync.aligned.m8n8.x4.shared.b16 {%0,%1,%2,%3}, [%4];"
                 : "=r"(r[0]), "=r"(r[1]), "=r"(r[2]), "=r"(r[3]) : "r"(addr));
}
__device__ __forceinline__ void ldsm4t(uint32_t* r, uint32_t addr) {
    asm volatile("ldmatrix.sync.aligned.m8n8.x4.trans.shared.b16 {%0,%1,%2,%3}, [%4];"
                 : "=r"(r[0]), "=r"(r[1]), "=r"(r[2]), "=r"(r[3]) : "r"(addr));
}
__device__ __forceinline__ void mma_f16(float* c, const uint32_t* a, const uint32_t* b) {
    asm volatile(
        "mma.sync.aligned.m16n8k16.row.col.f32.f16.f16.f32 "
        "{%0,%1,%2,%3}, {%4,%5,%6,%7}, {%8,%9}, {%0,%1,%2,%3};"
        : "+f"(c[0]), "+f"(c[1]), "+f"(c[2]), "+f"(c[3])
        : "r"(a[0]), "r"(a[1]), "r"(a[2]), "r"(a[3]), "r"(b[0]), "r"(b[1]));
}
__device__ __forceinline__ float sigm(float x) { return 1.0f / (1.0f + expf(-x)); }
__device__ __forceinline__ unsigned long long enc_max(float v, int t) {
    uint32_t u = __float_as_uint(v);
    u = (u & 0x80000000u) ? ~u : (u | 0x80000000u);
    return ((unsigned long long)u << 32) | (uint32_t)(TLEN - 1 - t);
}
__device__ __forceinline__ int dec_idx(unsigned long long s) {
    return TLEN - 1 - (int)(uint32_t)(s & 0xFFFFFFFFull);
}
__device__ __forceinline__ float dot4(float4 a, float4 b) {
    return a.x * b.x + a.y * b.y + a.z * b.z + a.w * b.w;
}

// ------------------------------------------------------------------
// prep: tiled transposes (all global accesses coalesced)
// ------------------------------------------------------------------
// UT[t][k] = U[k][t]; grid (K1PAD/32, TLEN/32), block (32,8)
__global__ void prep_UT(const float* __restrict__ U) {
    __shared__ float tile[32][33];
    int k0 = blockIdx.x * 32, t0 = blockIdx.y * 32;
    int tx = threadIdx.x, ty0 = threadIdx.y;
#pragma unroll
    for (int i = 0; i < 4; i++) {
        int tk = ty0 * 4 + i;
        int k = k0 + tk;
        tile[tk][tx] = (k < 2 * HD) ? U[(size_t)k * TLEN + t0 + tx] : 0.f;
    }
    __syncthreads();
#pragma unroll
    for (int i = 0; i < 4; i++) {
        int tt = ty0 * 4 + i;
        g_UT[t0 + tt][k0 + tx] = __float2half(tile[tx][tt]);
    }
}

// B1[net][k][n=h*16+p] = W1[net][p*HD+h][k]; grid (K1PAD/32, NPH/32, 2)
__global__ void prep_B1(const float* __restrict__ W1a, const float* __restrict__ W1b) {
    __shared__ float tile[32][33];
    int net = blockIdx.z;
    int k0 = blockIdx.x * 32, n0 = blockIdx.y * 32;
    int tx = threadIdx.x, ty0 = threadIdx.y;
    const float* W1 = net ? W1b : W1a;
#pragma unroll
    for (int i = 0; i < 4; i++) {
        int ty = ty0 * 4 + i;
        int n = n0 + ty;
        int h = n >> 4, p = n & 15;
        int k = k0 + tx;
        tile[ty][tx] = (k < 2 * HD) ? W1[(size_t)(p * HD + h) * 600 + k] : 0.f;
    }
    __syncthreads();
#pragma unroll
    for (int i = 0; i < 4; i++) {
        int ty = ty0 * 4 + i;
        g_B1[net][k0 + ty][n0 + tx] = __float2half(tile[tx][ty]);
    }
}

// B2[net][k][n=h*16+p] = W2[net][p*HD+h][k]; grid (K2PAD/32, NPH/32, 2)
__global__ void prep_B2(const float* __restrict__ W2a, const float* __restrict__ W2b) {
    __shared__ float tile[32][33];
    int net = blockIdx.z;
    int k0 = blockIdx.x * 32, n0 = blockIdx.y * 32;
    int tx = threadIdx.x, ty0 = threadIdx.y;
    const float* W2 = net ? W2b : W2a;
#pragma unroll
    for (int i = 0; i < 4; i++) {
        int ty = ty0 * 4 + i;
        int n = n0 + ty;
        int h = n >> 4, p = n & 15;
        int k = k0 + tx;
        tile[ty][tx] = (k < HD) ? W2[(size_t)(p * HD + h) * HD + k] : 0.f;
    }
    __syncthreads();
#pragma unroll
    for (int i = 0; i < 4; i++) {
        int ty = ty0 * 4 + i;
        g_B2[net][k0 + ty][n0 + tx] = __float2half(tile[tx][ty]);
    }
}

// misc: b2T transpose, m1 K-pad zero, state init
__global__ void prep_misc(const float* __restrict__ b2a, const float* __restrict__ b2b,
                          const float* __restrict__ h0,  const float* __restrict__ c0) {
    int idx0 = blockIdx.x * blockDim.x + threadIdx.x;
    int stride = gridDim.x * blockDim.x;
    for (int i = idx0; i < 2 * NPH; i += stride) {
        int net = i / NPH, n = i - net * NPH;
        int h = n >> 4, p = n & 15;
        const float* b2 = net ? b2b : b2a;
        g_b2T[net][n] = b2[p * HD + h];
    }
    for (int i = idx0; i < 2 * TLEN * (K2PAD - HD); i += stride) {
        int net = i / (TLEN * (K2PAD - HD));
        int rem = i - net * (TLEN * (K2PAD - HD));
        int t = rem / (K2PAD - HD);
        int k = HD + (rem - t * (K2PAD - HD));
        g_m1[net][t][k] = __float2half(0.f);
    }
    if (idx0 < HD) { g_hB[1][idx0] = h0[idx0]; g_cB[1][idx0] = c0[idx0]; }
}

// ------------------------------------------------------------------
// mma.sync GEMM: C[t][n] = sum_k A[t][k]*B[k][n]; single fp16 both sides.
// MODE 0: A=UT (K=416), B=B1 -> fp16 store to g_PU
// MODE 1: A=m1 (K=224), B=B2 -> +b2T, max over p -> g_m2[t][h]
// Block tile 128x128, 256 threads, 8 warps (4m x 2n), warp 32x64,
// K-chunk 32, 3-stage cp.async pipeline with wait_group 1.
// ------------------------------------------------------------------
#define A_ROW_B   80
#define A_STG_B   10240
#define B_ROW_B   272
#define B_STG_B   8704
#define OFF_B     30720              // 3 * A_STG_B
#define GEMM_SMEM (30720 + 26112)    // 3 A stages + 3 B stages = 56832

template <int MODE>
__global__ void __launch_bounds__(256) gemm_mma() {
    extern __shared__ char smem[];
    const int tid    = threadIdx.x;
    const int lane   = tid & 31;
    const int wid    = tid >> 5;
    const int warp_m = wid & 3;
    const int warp_n = wid >> 2;
    const int net    = blockIdx.z;
    const int m0     = blockIdx.x * 128;
    const int n0     = blockIdx.y * 128;
    const int KPAD   = (MODE == 0) ? K1PAD : K2PAD;
    const int NC     = KPAD / 32;

    const __half* __restrict__ Ap = (MODE == 0) ? &g_UT[0][0] : &g_m1[net][0][0];
    const __half* __restrict__ Bp = (MODE == 0) ? &g_B1[net][0][0] : &g_B2[net][0][0];

    const uint32_t sb = smem_u32(smem);

    const int arow = tid >> 1;
    const int aq   = (tid & 1) * 2;
    const int brow = tid >> 3;
    const int bq   = tid & 7;

    auto load_stage = [&](int stage, int kc) {
        const uint32_t as = sb + stage * A_STG_B + arow * A_ROW_B + aq * 16;
        const __half* ah = Ap + (size_t)(m0 + arow) * KPAD + kc + aq * 8;
        cp16(as,      ah);
        cp16(as + 16, ah + 8);
        const uint32_t bs = sb + OFF_B + stage * B_STG_B + brow * B_ROW_B + bq * 32;
        const __half* bg = Bp + (size_t)(kc + brow) * NPH + n0 + bq * 16;
        cp16(bs,      bg);
        cp16(bs + 16, bg + 8);
    };

    float acc[2][8][4];
#pragma unroll
    for (int i = 0; i < 2; i++)
#pragma unroll
        for (int j = 0; j < 8; j++)
#pragma unroll
            for (int q = 0; q < 4; q++) acc[i][j][q] = 0.f;

    const int l15 = lane & 15;
    const int l16 = (lane >> 4) * 8;
    const uint32_t aBase = sb + (warp_m * 32 + l15) * A_ROW_B + l16 * 2;
    const uint32_t bBase = sb + OFF_B + l15 * B_ROW_B + (warp_n * 64 + l16) * 2;

    load_stage(0, 0);
    CP_COMMIT();
    load_stage(1, 32);
    CP_COMMIT();

    for (int c = 0; c < NC; c++) {
        CP_WAIT1();               // stage c resident (at most 1 group in flight)
        __syncthreads();
        const int stg = c % 3;
        const uint32_t aS = aBase + stg * A_STG_B;
        const uint32_t bS = bBase + stg * B_STG_B;
#pragma unroll
        for (int s = 0; s < 2; s++) {
            uint32_t ah[2][4];
#pragma unroll
            for (int i = 0; i < 2; i++)
                ldsm4(ah[i], aS + i * 16 * A_ROW_B + s * 32);
#pragma unroll
            for (int half = 0; half < 2; half++) {
                uint32_t bb[4][2];
#pragma unroll
                for (int pr = 0; pr < 2; pr++) {
                    uint32_t r[4];
                    ldsm4t(r, bS + s * 16 * B_ROW_B + (half * 2 + pr) * 32);
                    bb[pr * 2][0] = r[0]; bb[pr * 2][1] = r[1];
                    bb[pr * 2 + 1][0] = r[2]; bb[pr * 2 + 1][1] = r[3];
                }
#pragma unroll
                for (int i = 0; i < 2; i++)
#pragma unroll
                    for (int j = 0; j < 4; j++)
                        mma_f16(acc[i][half * 4 + j], ah[i], bb[j]);
            }
        }
        if (c + 2 < NC) { load_stage((c + 2) % 3, (c + 2) * 32); }
        CP_COMMIT();              // commit (possibly empty) group to keep count in step
    }

    const int g4 = lane >> 2;
    const int t2 = (lane & 3) * 2;
    if (MODE == 0) {
        __half* C = &g_PU[net][0][0];
#pragma unroll
        for (int i = 0; i < 2; i++) {
            int r0 = m0 + warp_m * 32 + i * 16 + g4;
#pragma unroll
            for (int j = 0; j < 8; j++) {
                int col = n0 + warp_n * 64 + j * 8 + t2;
                *(__half2*)&C[(size_t)r0 * NPH + col] =
                    __floats2half2_rn(acc[i][j][0], acc[i][j][1]);
                *(__half2*)&C[(size_t)(r0 + 8) * NPH + col] =
                    __floats2half2_rn(acc[i][j][2], acc[i][j][3]);
            }
        }
    } else {
        float b2v[8][2];
#pragma unroll
        for (int j = 0; j < 8; j++) {
            int col = n0 + warp_n * 64 + j * 8 + t2;
            b2v[j][0] = __ldg(&g_b2T[net][col]);
            b2v[j][1] = __ldg(&g_b2T[net][col + 1]);
        }
        const int h0i = (n0 + warp_n * 64) >> 4;
#pragma unroll
        for (int i = 0; i < 2; i++) {
#pragma unroll
            for (int hh = 0; hh < 4; hh++) {
                float mlo = -3.4e38f, mhi = -3.4e38f;
#pragma unroll
                for (int jj = 0; jj < 2; jj++) {
                    int j = hh * 2 + jj;
                    mlo = fmaxf(mlo, fmaxf(acc[i][j][0] + b2v[j][0], acc[i][j][1] + b2v[j][1]));
                    mhi = fmaxf(mhi, fmaxf(acc[i][j][2] + b2v[j][0], acc[i][j][3] + b2v[j][1]));
                }
                mlo = fmaxf(mlo, __shfl_xor_sync(0xffffffffu, mlo, 1));
                mlo = fmaxf(mlo, __shfl_xor_sync(0xffffffffu, mlo, 2));
                mhi = fmaxf(mhi, __shfl_xor_sync(0xffffffffu, mhi, 1));
                mhi = fmaxf(mhi, __shfl_xor_sync(0xffffffffu, mhi, 2));
                if ((lane & 3) == 0) {
                    int row = m0 + warp_m * 32 + i * 16 + g4;
                    g_m2[net][row][h0i + hh]     = mlo;
                    g_m2[net][row + 8][h0i + hh] = mhi;
                }
            }
        }
    }
}

// ------------------------------------------------------------------
// LSTM gates: 8 rows/block, 1 warp per row, float4 dots
// ------------------------------------------------------------------
__global__ void lstm_gates(const float* __restrict__ U, const float* __restrict__ W_ih,
                           const float* __restrict__ W_hh, const float* __restrict__ b_ih,
                           const float* __restrict__ b_hh, int it) {
    __shared__ __align__(16) float xs[800];
    __shared__ __align__(16) float hs[HD];
    int tid = threadIdx.x;
    int s = (it == 0) ? 0 : dec_idx(g_slot[(it + 1) & 1][0]);
    int e = (it == 0) ? 0 : dec_idx(g_slot[(it + 1) & 1][1]);
    if (blockIdx.x == 0 && tid == 0) {
        g_slot[it & 1][0] = 0ull;
        g_slot[it & 1][1] = 0ull;
    }
    for (int j = tid; j < 800; j += 256)
        xs[j] = (j < 400) ? U[(size_t)j * TLEN + s] : U[(size_t)(j - 400) * TLEN + e];
    const float* hprev = g_hB[(it + 1) & 1];
    for (int j = tid; j < HD; j += 256) hs[j] = hprev[j];
    __syncthreads();
    int row = blockIdx.x * 8 + (tid >> 5);
    int lane = tid & 31;
    const float4* w4  = (const float4*)&W_ih[(size_t)row * 800];
    const float4* xs4 = (const float4*)xs;
    float acc = 0.f;
    for (int k = lane; k < 200; k += 32) acc += dot4(w4[k], xs4[k]);
    const float4* wh4 = (const float4*)&W_hh[(size_t)row * HD];
    const float4* hs4 = (const float4*)hs;
    if (lane < 25) {
        acc += dot4(wh4[lane], hs4[lane]);
        acc += dot4(wh4[lane + 25], hs4[lane + 25]);
    }
#pragma unroll
    for (int o = 16; o; o >>= 1) acc += __shfl_xor_sync(0xffffffffu, acc, o);
    if (lane == 0) g_g[row] = acc + b_ih[row] + b_hh[row];
}

// ------------------------------------------------------------------
// fused LSTM update + r = tanh(WD @ [h_new, u_s, u_e]); float4 dots
// ------------------------------------------------------------------
__global__ void r_kernel(const float* __restrict__ U, const float* __restrict__ WDa,
                         const float* __restrict__ WDb, int it) {
    __shared__ __align__(16) float vs[1000];
    int tid = threadIdx.x;
    int s = (it == 0) ? 0 : dec_idx(g_slot[(it + 1) & 1][0]);
    int e = (it == 0) ? 0 : dec_idx(g_slot[(it + 1) & 1][1]);
    if (tid < HD) {
        float gi = g_g[tid], gf = g_g[HD + tid], gg = g_g[2 * HD + tid], go = g_g[3 * HD + tid];
        float c = sigm(gf) * g_cB[(it + 1) & 1][tid] + sigm(gi) * tanhf(gg);
        float h = sigm(go) * tanhf(c);
        vs[tid] = h;
        if (blockIdx.x == 0) { g_cB[it & 1][tid] = c; g_hB[it & 1][tid] = h; }
    }
    for (int j = tid; j < 800; j += 256) {
        int jj = HD + j;
        vs[jj] = (j < 400) ? U[(size_t)j * TLEN + s] : U[(size_t)(j - 400) * TLEN + e];
    }
    __syncthreads();
    int row = blockIdx.x * 8 + (tid >> 5);
    int lane = tid & 31;
    int net = row / HD;
    int rr = row - net * HD;
    const float* WD = net ? WDb : WDa;
    const float4* w4  = (const float4*)&WD[(size_t)rr * 1000];
    const float4* vs4 = (const float4*)vs;
    float acc = 0.f;
    for (int k = lane; k < 250; k += 32) acc += dot4(w4[k], vs4[k]);
#pragma unroll
    for (int o = 16; o; o >>= 1) acc += __shfl_xor_sync(0xffffffffu, acc, o);
    if (lane == 0) g_r[net][rr] = tanhf(acc);
}

// ------------------------------------------------------------------
// prT[net][h*16+p] = W1r[p][h]@r + b1[p][h]; float4 dots
// ------------------------------------------------------------------
__global__ void pr_kernel(const float* __restrict__ W1a, const float* __restrict__ W1b,
                          const float* __restrict__ b1a, const float* __restrict__ b1b) {
    int o = blockIdx.x * 8 + (threadIdx.x >> 5);
    int lane = threadIdx.x & 31;
    int net = o / NPH;
    int n = o - net * NPH;
    int h = n >> 4, p = n & 15;
    const float* W1 = net ? W1b : W1a;
    const float* b1 = net ? b1b : b1a;
    const float4* w4 = (const float4*)&W1[(size_t)(p * HD + h) * 600 + 400];
    const float4* r4 = (const float4*)g_r[net];
    float acc = 0.f;
    if (lane < 25) {
        acc += dot4(w4[lane], r4[lane]);
        acc += dot4(w4[lane + 25], r4[lane + 25]);
    }
#pragma unroll
    for (int o2 = 16; o2; o2 >>= 1) acc += __shfl_xor_sync(0xffffffffu, acc, o2);
    if (lane == 0) g_prT[net][n] = acc + b1[p * HD + h];
}

// ------------------------------------------------------------------
// m1[t][h] = max_p(PU[t][h*16+p] + prT[h*16+p]) -> single fp16
// grid (TLEN/16, 2), 256 threads; 16B vector loads of PU
// ------------------------------------------------------------------
__global__ void m1_kernel() {
    int net = blockIdx.y;
    int t0 = blockIdx.x * 16;
    int tid = threadIdx.x;
    for (int item = tid; item < 16 * HD; item += 256) {
        int tt = item / HD, h = item - tt * HD;
        int t = t0 + tt;
        const uint4* pu4 = (const uint4*)&g_PU[net][t][h << 4];
        const float4* pr = (const float4*)&g_prT[net][h << 4];
        uint4 v0 = pu4[0], v1 = pu4[1];
        const __half2* a = (const __half2*)&v0;
        const __half2* b = (const __half2*)&v1;
        float m = -3.4e38f;
#pragma unroll
        for (int q = 0; q < 2; q++) {
            float4 pv = pr[q];
            float2 a0 = __half22float2(a[q * 2]);
            float2 a1 = __half22float2(a[q * 2 + 1]);
            m = fmaxf(m, fmaxf(fmaxf(a0.x + pv.x, a0.y + pv.y), fmaxf(a1.x + pv.z, a1.y + pv.w)));
        }
#pragma unroll
        for (int q = 0; q < 2; q++) {
            float4 pv = pr[2 + q];
            float2 a0 = __half22float2(b[q * 2]);
            float2 a1 = __half22float2(b[q * 2 + 1]);
            m = fmaxf(m, fmaxf(fmaxf(a0.x + pv.x, a0.y + pv.y), fmaxf(a1.x + pv.z, a1.y + pv.w)));
        }
        g_m1[net][t][h] = __float2half(m);
    }
}

// ------------------------------------------------------------------
// scores + fused argmax: 64 t per block, 512 threads (2 t per 16-lane group)
// ------------------------------------------------------------------
#define SCORE_SMEM ((64 * 408 + 16 * 401 + 128) * 4)
__global__ void __launch_bounds__(512) score_kernel(
        const float* __restrict__ W3a, const float* __restrict__ W3b,
        const float* __restrict__ b3a, const float* __restrict__ b3b,
        float* __restrict__ out, int it, int maxI) {
    extern __shared__ float sm[];
    float* ms  = sm;                 // [64][408]
    float* w3s = sm + 64 * 408;      // [16][401]
    float* bmx = w3s + 16 * 401;     // [64]
    int*   bmi = (int*)(bmx + 64);   // [64]
    int net = blockIdx.y;
    int t0 = blockIdx.x * 64;
    int tid = threadIdx.x;
    const float* W3 = net ? W3b : W3a;
    for (int idx = tid; idx < 6400; idx += 512) {
        int p = idx / 400, d = idx - p * 400;
        w3s[p * 401 + d] = W3[p * 400 + d];
    }
    for (int idx = tid; idx < 64 * HD; idx += 512) {
        int tt = idx / HD, h = idx - tt * HD;
        int t = t0 + tt;
        ms[tt * 408 + h] = __half2float(g_m1[net][t][h]);
        ms[tt * 408 + 200 + h] = g_m2[net][t][h];
    }
    __syncthreads();
    int grp = tid >> 4, p = tid & 15;
    float bias = (net ? b3b : b3a)[p];
    const float* w3r = &w3s[p * 401];
#pragma unroll
    for (int rep = 0; rep < 2; rep++) {
        int tt = grp + rep * 32;
        float acc = bias;
        const float* msr = &ms[tt * 408];
#pragma unroll 4
        for (int d = 0; d < 400; d++) acc = fmaf(msr[d], w3r[d], acc);
#pragma unroll
        for (int o = 8; o; o >>= 1) acc = fmaxf(acc, __shfl_xor_sync(0xffffffffu, acc, o));
        if (p == 0) {
            out[((size_t)net * maxI + it) * TLEN + t0 + tt] = acc;
            bmx[tt] = acc;
            bmi[tt] = t0 + tt;
        }
    }
    __syncthreads();
    if (tid == 0) {
        float bv = bmx[0]; int bi = bmi[0];
        for (int q = 1; q < 64; q++) {
            if (bmx[q] > bv) { bv = bmx[q]; bi = bmi[q]; }
        }
        atomicMax(&g_slot[it & 1][net], enc_max(bv, bi));
    }
}

__global__ void finalize_kernel(float* __restrict__ out, int maxI) {
    out[(size_t)2 * maxI * TLEN + 0] = (float)dec_idx(g_slot[(maxI - 1) & 1][0]);
    out[(size_t)2 * maxI * TLEN + 1] = (float)dec_idx(g_slot[(maxI - 1) & 1][1]);
}

// ------------------------------------------------------------------
// launch
// ------------------------------------------------------------------
extern "C" void kernel_launch(void* const* d_in, const int* in_sizes, int n_in,
                              void* d_out, int out_size) {
    const float* U    = (const float*)d_in[0];
    const float* h0   = (const float*)d_in[2];
    const float* c0   = (const float*)d_in[3];
    const float* W_ih = (const float*)d_in[4];
    const float* W_hh = (const float*)d_in[5];
    const float* b_ih = (const float*)d_in[6];
    const float* b_hh = (const float*)d_in[7];
    const float* WD_a = (const float*)d_in[8];
    const float* W1_a = (const float*)d_in[9];
    const float* b1_a = (const float*)d_in[10];
    const float* W2_a = (const float*)d_in[11];
    const float* b2_a = (const float*)d_in[12];
    const float* W3_a = (const float*)d_in[13];
    const float* b3_a = (const float*)d_in[14];
    const float* WD_b = (const float*)d_in[15];
    const float* W1_b = (const float*)d_in[16];
    const float* b1_b = (const float*)d_in[17];
    const float* W2_b = (const float*)d_in[18];
    const float* b2_b = (const float*)d_in[19];
    const float* W3_b = (const float*)d_in[20];
    const float* b3_b = (const float*)d_in[21];
    float* out = (float*)d_out;

    int maxI = out_size / (2 * TLEN);
    if (maxI < 1) maxI = 1;
    int write_se = (out_size >= 2 * maxI * TLEN + 2) ? 1 : 0;

    cudaFuncSetAttribute(gemm_mma<0>, cudaFuncAttributeMaxDynamicSharedMemorySize, GEMM_SMEM);
    cudaFuncSetAttribute(gemm_mma<1>, cudaFuncAttributeMaxDynamicSharedMemorySize, GEMM_SMEM);
    cudaFuncSetAttribute(score_kernel, cudaFuncAttributeMaxDynamicSharedMemorySize, SCORE_SMEM);

    prep_UT<<<dim3(K1PAD / 32, TLEN / 32), dim3(32, 8)>>>(U);
    prep_B1<<<dim3(K1PAD / 32, NPH / 32, 2), dim3(32, 8)>>>(W1_a, W1_b);
    prep_B2<<<dim3(K2PAD / 32, NPH / 32, 2), dim3(32, 8)>>>(W2_a, W2_b);
    prep_misc<<<128, 256>>>(b2_a, b2_b, h0, c0);
    gemm_mma<0><<<dim3(TLEN / 128, NPH / 128, 2), 256, GEMM_SMEM>>>();

    for (int it = 0; it < maxI; it++) {
        lstm_gates<<<100, 256>>>(U, W_ih, W_hh, b_ih, b_hh, it);
        r_kernel<<<50, 256>>>(U, WD_a, WD_b, it);
        pr_kernel<<<800, 256>>>(W1_a, W1_b, b1_a, b1_b);
        m1_kernel<<<dim3(TLEN / 16, 2), 256>>>();
        gemm_mma<1><<<dim3(TLEN / 128, NPH / 128, 2), 256, GEMM_SMEM>>>();
        score_kernel<<<dim3(TLEN / 64, 2), 512, SCORE_SMEM>>>(W3_a, W3_b, b3_a, b3_b, out, it, maxI);
    }
    if (write_se) finalize_kernel<<<1, 1>>>(out, maxI);
}